// round 13
// baseline (speedup 1.0000x reference)
#include <cuda_runtime.h>
#include <cuda_bf16.h>
#include <cstdint>
#include <math.h>

#define NVOX   500000
#define CCH    64
#define KTAPS  27
#define SBLK   512
#define SCGRID 2048
#define FBLK   1664    // fill blocks (26 taps * 64)
#define MAXTIL 110000

// ---------------- static device scratch (no allocs allowed) -----------------
__device__ float g_buf1[(size_t)NVOX * CCH];      // conv out fp32 (pre-BN)
__device__ uint4 g_xhi[(size_t)NVOX * 8];         // bf16 hi features [n][64]
__device__ uint4 g_xlo[(size_t)NVOX * 8];         // bf16 lo features [n][64]
__device__ uint4 g_wt1[KTAPS * 1024];             // W1^T bf16 hi/lo, swizzled
__device__ uint4 g_wt2[KTAPS * 1024];             // W2^T bf16 hi/lo, swizzled
__device__ float g_part[SBLK * 128];
__device__ float g_stats[128];
__device__ int2  g_pairs[(size_t)NVOX * KTAPS];   // compacted (out,in), padded/128
__device__ int   g_bcnt[26 * 512];                // per (tap, block, warp) counts
__device__ int   g_boff[26 * 512];                // absolute output offsets
__device__ int   g_meta[128];   // [0..26]=tile-base prefix (tb[26]=ntiles), [64+kk]=cnt
__device__ int   g_tmap[MAXTIL];                  // layer-major order -> tile id
__device__ int   g_ttap[MAXTIL];                  // layer-major order -> tap k

// ---------------- helpers ----------------------------------------------------
__device__ __forceinline__ uint32_t smem_u32(const void* p) {
    uint32_t a;
    asm("{ .reg .u64 t; cvta.to.shared.u64 t, %1; cvt.u32.u64 %0, t; }" : "=r"(a) : "l"(p));
    return a;
}
__device__ __host__ __forceinline__ uint32_t sw128(uint32_t off) {
    return off ^ ((off >> 3) & 0x70);
}
__device__ __forceinline__ void ldm_x4(uint32_t* r, uint32_t addr) {
    asm volatile("ldmatrix.sync.aligned.m8n8.x4.shared.b16 {%0,%1,%2,%3}, [%4];"
                 : "=r"(r[0]), "=r"(r[1]), "=r"(r[2]), "=r"(r[3]) : "r"(addr));
}
__device__ __forceinline__ void mma_bf16(float* d, const uint32_t* a,
                                         uint32_t b0, uint32_t b1) {
    asm volatile("mma.sync.aligned.m16n8k16.row.col.f32.bf16.bf16.f32 "
                 "{%0,%1,%2,%3}, {%4,%5,%6,%7}, {%8,%9}, {%0,%1,%2,%3};"
                 : "+f"(d[0]), "+f"(d[1]), "+f"(d[2]), "+f"(d[3])
                 : "r"(a[0]), "r"(a[1]), "r"(a[2]), "r"(a[3]), "r"(b0), "r"(b1));
}
__device__ __forceinline__ void cpa16(uint32_t dst, const void* src, uint32_t sz) {
    asm volatile("cp.async.cg.shared.global [%0], [%1], 16, %2;"
                 :: "r"(dst), "l"(src), "r"(sz) : "memory");
}
#define CP_COMMIT() asm volatile("cp.async.commit_group;" ::: "memory")
#define CP_WAIT0()  asm volatile("cp.async.wait_group 0;" ::: "memory")
// 16B vector reduction: one L2 transaction, 4 adds
__device__ __forceinline__ void redadd4(float* p, float x, float y, float z, float w) {
    asm volatile("red.global.v4.f32.add [%0], {%1,%2,%3,%4};"
                 :: "l"(p), "f"(x), "f"(y), "f"(z), "f"(w) : "memory");
}

// shared 3-pass MMA over one 128x64x64 tile (A hi/lo, W hi/lo in smem)
__device__ __forceinline__ void tile_mma(
    uint32_t ab, uint32_t lb, uint32_t wh, uint32_t wl,
    const uint32_t aoff[4][2], const uint32_t boff[4][2], float acc[2][4][4])
{
    #pragma unroll
    for (int kc = 0; kc < 4; ++kc) {
        uint32_t ah[2][4], al[2][4], bh[2][4], bl[2][4];
        #pragma unroll
        for (int mi = 0; mi < 2; ++mi) {
            ldm_x4(ah[mi], ab + aoff[kc][mi]);
            ldm_x4(al[mi], lb + aoff[kc][mi]);
        }
        #pragma unroll
        for (int ni = 0; ni < 2; ++ni) {
            ldm_x4(bh[ni], wh + boff[kc][ni]);
            ldm_x4(bl[ni], wl + boff[kc][ni]);
        }
        #pragma unroll
        for (int mi = 0; mi < 2; ++mi)
            #pragma unroll
            for (int nt = 0; nt < 4; ++nt) {
                int ni = nt >> 1, s = nt & 1;
                mma_bf16(acc[mi][nt], ah[mi], bh[ni][s], bh[ni][s + 2]);
                mma_bf16(acc[mi][nt], ah[mi], bl[ni][s], bl[ni][s + 2]);
                mma_bf16(acc[mi][nt], al[mi], bh[ni][s], bh[ni][s + 2]);
            }
    }
}

// ---------------- split fp32 -> bf16 hi/lo ------------------------------------
__device__ __forceinline__ void split8(const float4& a, const float4& b,
                                       uint4& h, uint4& l)
{
    __nv_bfloat162 h0 = __floats2bfloat162_rn(a.x, a.y);
    __nv_bfloat162 h1 = __floats2bfloat162_rn(a.z, a.w);
    __nv_bfloat162 h2 = __floats2bfloat162_rn(b.x, b.y);
    __nv_bfloat162 h3 = __floats2bfloat162_rn(b.z, b.w);
    float2 f0 = __bfloat1622float2(h0), f1 = __bfloat1622float2(h1);
    float2 f2 = __bfloat1622float2(h2), f3 = __bfloat1622float2(h3);
    __nv_bfloat162 l0 = __floats2bfloat162_rn(a.x - f0.x, a.y - f0.y);
    __nv_bfloat162 l1 = __floats2bfloat162_rn(a.z - f1.x, a.w - f1.y);
    __nv_bfloat162 l2 = __floats2bfloat162_rn(b.x - f2.x, b.y - f2.y);
    __nv_bfloat162 l3 = __floats2bfloat162_rn(b.z - f3.x, b.w - f3.y);
    h = make_uint4(*(uint32_t*)&h0, *(uint32_t*)&h1, *(uint32_t*)&h2, *(uint32_t*)&h3);
    l = make_uint4(*(uint32_t*)&l0, *(uint32_t*)&l1, *(uint32_t*)&l2, *(uint32_t*)&l3);
}

// ---------------- fused prep+count: W split, x split, tap counts -------------
__global__ __launch_bounds__(256) void prepcount_kernel(
    const float* __restrict__ W1, const float* __restrict__ W2,
    const float* __restrict__ x, const float* __restrict__ valid,
    int nchunk, int xb, int n)
{
    const int b = blockIdx.x;
    if (b < 54) {
        const int k = (b < 27) ? b : b - 27;
        const float* W = (b < 27) ? W1 : W2;
        uint4* wt = (b < 27) ? g_wt1 : g_wt2;
        char* dst = (char*)(wt + (size_t)k * 1024);
        for (int e = threadIdx.x; e < CCH * CCH; e += 256) {
            int ci = e >> 6, co = e & 63;
            float w = W[(size_t)k * CCH * CCH + e];
            __nv_bfloat16 h = __float2bfloat16(w);
            __nv_bfloat16 l = __float2bfloat16(w - __bfloat162float(h));
            uint32_t off = sw128((uint32_t)(co * 128 + ci * 2));
            *(__nv_bfloat16*)(dst + off) = h;
            *(__nv_bfloat16*)(dst + 8192 + off) = l;
        }
    } else if (b < 54 + xb) {
        int i = (b - 54) * 256 + threadIdx.x;
        if (i >= nchunk) return;
        const float4* x4 = (const float4*)x;
        float4 a = x4[2 * i], c = x4[2 * i + 1];
        uint4 h, l;
        split8(a, c, h, l);
        g_xhi[i] = h; g_xlo[i] = l;
    } else {
        const int cb = b - 54 - xb;
        const int kk = cb >> 6, bb = cb & 63;
        const int k = kk + (kk >= 13 ? 1 : 0);
        const int chunk = (n + 63) >> 6;
        const int r0 = bb * chunk, r1 = min(r0 + chunk, n);
        const int lane = threadIdx.x & 31, w = threadIdx.x >> 5;
        const int wc = (chunk + 7) >> 3;
        const int ws = r0 + w * wc, we = min(ws + wc, r1);
        const size_t kb = (size_t)k * n;
        int c = 0;
        for (int s = ws; s < we; s += 32) {
            int i = s + lane;
            bool v = (i < we) && (valid[kb + i] != 0.f);
            c += __popc(__ballot_sync(0xffffffffu, v));
        }
        if (lane == 0)
            g_bcnt[(size_t)cb * 8 + w] = c;
    }
}

// scan + build layer-major tile order map
__global__ __launch_bounds__(1024) void scan_kernel()
{
    __shared__ int stot[26];
    __shared__ int stb[27];
    const int tid = threadIdx.x, wid = tid >> 5, lane = tid & 31;
    int v[16], lexcl = 0;
    if (wid < 26) {
        const int base = wid * 512 + lane * 16;
        int s = 0;
        #pragma unroll
        for (int j = 0; j < 16; ++j) { v[j] = g_bcnt[base + j]; s += v[j]; }
        int p = s;
        #pragma unroll
        for (int d = 1; d < 32; d <<= 1) {
            int t = __shfl_up_sync(0xffffffffu, p, d);
            if (lane >= d) p += t;
        }
        lexcl = p - s;
        int tot = __shfl_sync(0xffffffffu, p, 31);
        if (lane == 0) stot[wid] = tot;
    }
    __syncthreads();
    if (tid == 0) {
        int tb = 0;
        for (int kk = 0; kk < 26; ++kk) {
            stb[kk] = tb;
            tb += (stot[kk] + 127) >> 7;
            g_meta[64 + kk] = stot[kk];
        }
        stb[26] = tb;
        for (int kk = 0; kk <= 26; ++kk) g_meta[kk] = stb[kk];
    }
    __syncthreads();
    if (wid < 26) {
        const int base = wid * 512 + lane * 16;
        int off = stb[wid] * 128 + lexcl;
        #pragma unroll
        for (int j = 0; j < 16; ++j) { g_boff[base + j] = off; off += v[j]; }
    }
    // build layer-major tile map: pos(kk,j) = sum_q min(tiles_q, j) + #{q<kk : tiles_q > j}
    for (int kk = 0; kk < 26; ++kk) {
        const int tk = stb[kk + 1] - stb[kk];
        for (int j = tid; j < tk; j += 1024) {
            int pos = 0;
            #pragma unroll
            for (int q = 0; q < 26; ++q) {
                int tq = stb[q + 1] - stb[q];
                pos += min(tq, j);
                pos += (q < kk && tq > j) ? 1 : 0;
            }
            g_tmap[pos] = stb[kk] + j;
            g_ttap[pos] = kk + (kk >= 13 ? 1 : 0);
        }
    }
}

// ---------------- fused fill + center1 ----------------------------------------
#define CEN_SMEM 49152
__global__ __launch_bounds__(256, 2) void fillcen_kernel(
    const int* __restrict__ nbr, const float* __restrict__ valid,
    const uint4* __restrict__ xhi, const uint4* __restrict__ xlo,
    const uint4* __restrict__ wtap, float* __restrict__ out, int n)
{
    if (blockIdx.x < FBLK) {
        const int cb = blockIdx.x;
        const int kk = cb >> 6, bb = cb & 63;
        const int k = kk + (kk >= 13 ? 1 : 0);
        const int chunk = (n + 63) >> 6;
        const int r0 = bb * chunk, r1 = min(r0 + chunk, n);
        const int lane = threadIdx.x & 31, w = threadIdx.x >> 5;
        const int wc = (chunk + 7) >> 3;
        const int ws = r0 + w * wc, we = min(ws + wc, r1);
        const size_t kb = (size_t)k * n;

        int off = g_boff[(size_t)cb * 8 + w];
        for (int s = ws; s < we; s += 32) {
            int i = s + lane;
            bool v = (i < we) && (valid[kb + i] != 0.f);
            unsigned bal = __ballot_sync(0xffffffffu, v);
            if (v)
                g_pairs[off + __popc(bal & ((1u << lane) - 1u))] = make_int2(i, nbr[kb + i]);
            off += __popc(bal);
        }
        if (bb == 63) {
            const int cnt = g_meta[64 + kk];
            const int sbase = g_meta[kk] * 128;
            const int padded = (g_meta[kk + 1] - g_meta[kk]) * 128;
            for (int s = cnt + threadIdx.x; s < padded; s += 256)
                g_pairs[sbase + s] = make_int2(0, -1);
        }
        return;
    }

    // center part: dense identity-tap GEMM, plain writes
    extern __shared__ char smem[];
    const uint32_t sb = smem_u32(smem);
    const int tid = threadIdx.x, lane = tid & 31, wid = tid >> 5;
    const int n0 = (blockIdx.x - FBLK) * 128;
    const int m0 = (wid & 3) * 32, nb0 = (wid >> 2) * 32;
    const int frow = tid >> 1, fhalf = tid & 1;

    const int g = n0 + frow;
    const uint32_t sz = (g < n) ? 16u : 0u;
    const int gc = min(g, n - 1);
    const char* sh = (const char*)(xhi + (size_t)gc * 8);
    const char* sl = (const char*)(xlo + (size_t)gc * 8);
    #pragma unroll
    for (int j = 0; j < 4; ++j) {
        int c = fhalf * 4 + j;
        uint32_t so = sw128((uint32_t)(frow * 128 + c * 16));
        cpa16(sb + so, sh + c * 16, sz);
        cpa16(sb + 16384 + so, sl + c * 16, sz);
    }
    const char* ws = (const char*)wtap;
    #pragma unroll
    for (int j = 0; j < 2; ++j) {
        int c = tid + j * 256;
        cpa16(sb + 32768 + c * 16, ws + c * 16, 16);
        cpa16(sb + 40960 + c * 16, ws + 8192 + c * 16, 16);
    }
    CP_COMMIT(); CP_WAIT0();
    __syncthreads();

    const uint32_t arow = lane & 15, agrp = (lane >> 4) * 16;
    uint32_t aoff[4][2], boff[4][2];
    #pragma unroll
    for (int kc = 0; kc < 4; ++kc) {
        #pragma unroll
        for (int mi = 0; mi < 2; ++mi)
            aoff[kc][mi] = sw128((uint32_t)((m0 + mi * 16 + arow) * 128 + kc * 32) + agrp);
        #pragma unroll
        for (int ni = 0; ni < 2; ++ni)
            boff[kc][ni] = sw128((uint32_t)((nb0 + ni * 16 + arow) * 128 + kc * 32) + agrp);
    }

    float acc[2][4][4];
    #pragma unroll
    for (int i = 0; i < 2; ++i)
        #pragma unroll
        for (int j = 0; j < 4; ++j)
            #pragma unroll
            for (int q = 0; q < 4; ++q) acc[i][j][q] = 0.f;

    tile_mma(sb, sb + 16384, sb + 32768, sb + 40960, aoff, boff, acc);

    const int rq = lane >> 2, cq = (lane & 3) * 2;
    #pragma unroll
    for (int mi = 0; mi < 2; ++mi)
        #pragma unroll
        for (int nt = 0; nt < 4; ++nt) {
            int col = nb0 + nt * 8 + cq;
            int r0 = n0 + m0 + mi * 16 + rq;
            if (r0 < n)
                *(float2*)(out + (size_t)r0 * CCH + col) = make_float2(acc[mi][nt][0], acc[mi][nt][1]);
            int r1 = r0 + 8;
            if (r1 < n)
                *(float2*)(out + (size_t)r1 * CCH + col) = make_float2(acc[mi][nt][2], acc[mi][nt][3]);
        }
}

// ---------------- standalone center (conv2) ------------------------------------
__global__ __launch_bounds__(256, 2) void center_kernel(
    const uint4* __restrict__ xhi, const uint4* __restrict__ xlo,
    const uint4* __restrict__ wtap, float* __restrict__ out, int n)
{
    extern __shared__ char smem[];
    const uint32_t sb = smem_u32(smem);
    const int tid = threadIdx.x, lane = tid & 31, wid = tid >> 5;
    const int n0 = blockIdx.x * 128;
    const int m0 = (wid & 3) * 32, nb0 = (wid >> 2) * 32;
    const int frow = tid >> 1, fhalf = tid & 1;

    const int g = n0 + frow;
    const uint32_t sz = (g < n) ? 16u : 0u;
    const int gc = min(g, n - 1);
    const char* sh = (const char*)(xhi + (size_t)gc * 8);
    const char* sl = (const char*)(xlo + (size_t)gc * 8);
    #pragma unroll
    for (int j = 0; j < 4; ++j) {
        int c = fhalf * 4 + j;
        uint32_t so = sw128((uint32_t)(frow * 128 + c * 16));
        cpa16(sb + so, sh + c * 16, sz);
        cpa16(sb + 16384 + so, sl + c * 16, sz);
    }
    const char* ws = (const char*)wtap;
    #pragma unroll
    for (int j = 0; j < 2; ++j) {
        int c = tid + j * 256;
        cpa16(sb + 32768 + c * 16, ws + c * 16, 16);
        cpa16(sb + 40960 + c * 16, ws + 8192 + c * 16, 16);
    }
    CP_COMMIT(); CP_WAIT0();
    __syncthreads();

    const uint32_t arow = lane & 15, agrp = (lane >> 4) * 16;
    uint32_t aoff[4][2], boff[4][2];
    #pragma unroll
    for (int kc = 0; kc < 4; ++kc) {
        #pragma unroll
        for (int mi = 0; mi < 2; ++mi)
            aoff[kc][mi] = sw128((uint32_t)((m0 + mi * 16 + arow) * 128 + kc * 32) + agrp);
        #pragma unroll
        for (int ni = 0; ni < 2; ++ni)
            boff[kc][ni] = sw128((uint32_t)((nb0 + ni * 16 + arow) * 128 + kc * 32) + agrp);
    }

    float acc[2][4][4];
    #pragma unroll
    for (int i = 0; i < 2; ++i)
        #pragma unroll
        for (int j = 0; j < 4; ++j)
            #pragma unroll
            for (int q = 0; q < 4; ++q) acc[i][j][q] = 0.f;

    tile_mma(sb, sb + 16384, sb + 32768, sb + 40960, aoff, boff, acc);

    const int rq = lane >> 2, cq = (lane & 3) * 2;
    #pragma unroll
    for (int mi = 0; mi < 2; ++mi)
        #pragma unroll
        for (int nt = 0; nt < 4; ++nt) {
            int col = nb0 + nt * 8 + cq;
            int r0 = n0 + m0 + mi * 16 + rq;
            if (r0 < n)
                *(float2*)(out + (size_t)r0 * CCH + col) = make_float2(acc[mi][nt][0], acc[mi][nt][1]);
            int r1 = r0 + 8;
            if (r1 < n)
                *(float2*)(out + (size_t)r1 * CCH + col) = make_float2(acc[mi][nt][2], acc[mi][nt][3]);
        }
}

// ---------------- scatter conv: layer-major tiles + vector RED ----------------
#define SCA(s)     ((s) * 32768)            // hi 16KB + lo 16KB
#define SCW(s)     (65536 + (s) * 16384)    // hi 8KB + lo 8KB
#define SCP(ps)    (98304 + (ps) * 1024)    // pairs, 3 stages
#define SC_SMEM    101504

__global__ __launch_bounds__(256, 2) void scatter_kernel(
    const uint4* __restrict__ xhi, const uint4* __restrict__ xlo,
    const uint4* __restrict__ wt, float* __restrict__ out)
{
    extern __shared__ char smem[];
    const uint32_t sb = smem_u32(smem);
    const int tid = threadIdx.x, lane = tid & 31, wid = tid >> 5;
    const int m0 = (wid & 3) * 32, nb0 = (wid >> 2) * 32;
    const int frow = tid >> 1, fhalf = tid & 1;

    const int ntiles = g_meta[26];
    int u = blockIdx.x;
    if (u >= ntiles) return;

    // precomputed offsets
    const uint32_t arow = lane & 15, agrp = (lane >> 4) * 16;
    uint32_t aoff[4][2], boff[4][2];
    #pragma unroll
    for (int kc = 0; kc < 4; ++kc) {
        #pragma unroll
        for (int mi = 0; mi < 2; ++mi)
            aoff[kc][mi] = sw128((uint32_t)((m0 + mi * 16 + arow) * 128 + kc * 32) + agrp);
        #pragma unroll
        for (int ni = 0; ni < 2; ++ni)
            boff[kc][ni] = sw128((uint32_t)((nb0 + ni * 16 + arow) * 128 + kc * 32) + agrp);
    }
    uint32_t so4[4];
    #pragma unroll
    for (int j = 0; j < 4; ++j)
        so4[j] = sw128((uint32_t)(frow * 128 + (fhalf * 4 + j) * 16));

    auto issuePairs = [&](int uu, int ps) {
        int tt = __ldg(&g_tmap[uu]);
        if (tid < 64)
            cpa16(sb + SCP(ps) + tid * 16,
                  (const char*)(g_pairs + (size_t)tt * 128) + tid * 16, 16);
    };
    auto issueA = [&](int s, int ps) {
        const int2* prs = (const int2*)(smem + SCP(ps));
        int in = prs[frow].y;
        uint32_t sz = (in >= 0) ? 16u : 0u;
        int ic = (in >= 0) ? in : 0;
        const char* sh = (const char*)(xhi + (size_t)ic * 8);
        const char* sl = (const char*)(xlo + (size_t)ic * 8);
        #pragma unroll
        for (int j = 0; j < 4; ++j) {
            int c = fhalf * 4 + j;
            cpa16(sb + SCA(s) + so4[j], sh + c * 16, sz);
            cpa16(sb + SCA(s) + 16384 + so4[j], sl + c * 16, sz);
        }
    };
    auto issueW = [&](int s, int uu) {
        int k = __ldg(&g_ttap[uu]);
        const char* ws = (const char*)(wt + (size_t)k * 1024);
        #pragma unroll
        for (int j = 0; j < 2; ++j) {
            int c = tid + j * 256;
            cpa16(sb + SCW(s) + c * 16, ws + c * 16, 16);
            cpa16(sb + SCW(s) + 8192 + c * 16, ws + 8192 + c * 16, 16);
        }
    };

    // prologue
    issuePairs(u, 0);
    if (u + SCGRID < ntiles) issuePairs(u + SCGRID, 1);
    CP_COMMIT(); CP_WAIT0();
    __syncthreads();
    issueA(0, 0);
    issueW(0, u);
    CP_COMMIT();

    const int rq = lane >> 2;
    const int cb = (lane & 2) * 2;       // 0 or 4: v4 column base within 8-col tile
    const bool evn = !(lane & 1);
    int i = 0;
    while (true) {
        const int s = i & 1;
        const int ps = i % 3;
        CP_WAIT0();
        __syncthreads();

        int un = u + SCGRID;
        bool hn = (un < ntiles);
        if (hn) {
            issueA(s ^ 1, (i + 1) % 3);
            issueW(s ^ 1, un);
            int un2 = un + SCGRID;
            if (un2 < ntiles) issuePairs(un2, (i + 2) % 3);
            CP_COMMIT();
        }

        float acc[2][4][4];
        #pragma unroll
        for (int a = 0; a < 2; ++a)
            #pragma unroll
            for (int b = 0; b < 4; ++b)
                #pragma unroll
                for (int q = 0; q < 4; ++q) acc[a][b][q] = 0.f;

        tile_mma(sb + SCA(s), sb + SCA(s) + 16384, sb + SCW(s), sb + SCW(s) + 8192,
                 aoff, boff, acc);

        // epilogue: butterfly lanes (l, l^1) to form 16B vectors, one v4 RED each
        const int2* prs = (const int2*)(smem + SCP(ps));
        #pragma unroll
        for (int mi = 0; mi < 2; ++mi) {
            int r = m0 + mi * 16 + rq;
            int2 p0 = prs[r];
            int2 p1 = prs[r + 8];
            float* o0 = out + (size_t)p0.x * CCH;
            float* o1 = out + (size_t)p1.x * CCH;
            #pragma unroll
            for (int nt = 0; nt < 4; ++nt) {
                float a0 = acc[mi][nt][0], a1 = acc[mi][nt][1];
                float a2 = acc[mi][nt][2], a3 = acc[mi][nt][3];
                float b0 = __shfl_xor_sync(0xffffffffu, a0, 1);
                float b1 = __shfl_xor_sync(0xffffffffu, a1, 1);
                float b2 = __shfl_xor_sync(0xffffffffu, a2, 1);
                float b3 = __shfl_xor_sync(0xffffffffu, a3, 1);
                int col = nb0 + nt * 8 + cb;
                if (evn) {
                    if (p0.y >= 0) redadd4(o0 + col, a0, a1, b0, b1);
                } else {
                    if (p1.y >= 0) redadd4(o1 + col, b2, b3, a2, a3);
                }
            }
        }
        if (!hn) break;
        u = un;
        ++i;
    }
}

// ---------------- bnrelu: BN + ReLU fused, writes bf16 hi/lo -------------------
__global__ __launch_bounds__(256) void bnrelu_kernel(const float* __restrict__ x, int nchunk)
{
    int i = blockIdx.x * blockDim.x + threadIdx.x;
    if (i >= nchunk) return;
    const float4* x4 = (const float4*)x;
    float4 a = x4[2 * i], b = x4[2 * i + 1];
    int c = (i * 8) & 63;
    a.x = fmaxf(a.x * g_stats[c + 0] + g_stats[64 + c + 0], 0.f);
    a.y = fmaxf(a.y * g_stats[c + 1] + g_stats[64 + c + 1], 0.f);
    a.z = fmaxf(a.z * g_stats[c + 2] + g_stats[64 + c + 2], 0.f);
    a.w = fmaxf(a.w * g_stats[c + 3] + g_stats[64 + c + 3], 0.f);
    b.x = fmaxf(b.x * g_stats[c + 4] + g_stats[64 + c + 4], 0.f);
    b.y = fmaxf(b.y * g_stats[c + 5] + g_stats[64 + c + 5], 0.f);
    b.z = fmaxf(b.z * g_stats[c + 6] + g_stats[64 + c + 6], 0.f);
    b.w = fmaxf(b.w * g_stats[c + 7] + g_stats[64 + c + 7], 0.f);
    uint4 h, l;
    split8(a, b, h, l);
    g_xhi[i] = h; g_xlo[i] = l;
}

// ---------------- BN stats (deterministic) ------------------------------------
__global__ __launch_bounds__(256) void stats_kernel(const float* __restrict__ buf, int n)
{
    __shared__ float s[4][128];
    const int tid = threadIdx.x, lane = tid & 63, grp = tid >> 6;
    const int chunk = (n + SBLK - 1) / SBLK;
    const int r0 = blockIdx.x * chunk;
    const int r1 = min(r0 + chunk, n);
    float sm = 0.f, sq = 0.f;
    for (int r = r0 + grp; r < r1; r += 4) {
        float v = buf[(size_t)r * CCH + lane];
        sm += v; sq += v * v;
    }
    s[grp][lane] = sm; s[grp][64 + lane] = sq;
    __syncthreads();
    if (tid < 128)
        g_part[(size_t)blockIdx.x * 128 + tid] = s[0][tid] + s[1][tid] + s[2][tid] + s[3][tid];
}

__global__ __launch_bounds__(512) void reduce_kernel(
    const float* __restrict__ gamma, const float* __restrict__ beta, int n)
{
    __shared__ float s[4][128];
    const int tid = threadIdx.x, col = tid & 127, grp = tid >> 7;
    float acc = 0.f;
    for (int b = grp; b < SBLK; b += 4) acc += g_part[(size_t)b * 128 + col];
    s[grp][col] = acc;
    __syncthreads();
    if (tid < 128) s[0][tid] = s[0][tid] + s[1][tid] + s[2][tid] + s[3][tid];
    __syncthreads();
    if (tid < 64) {
        float inv_n = 1.0f / (float)n;
        float mean = s[0][tid] * inv_n;
        float var = s[0][64 + tid] * inv_n - mean * mean;
        float scale = gamma[tid] * rsqrtf(var + 1e-5f);
        g_stats[tid] = scale;
        g_stats[64 + tid] = beta[tid] - mean * scale;
    }
}

// ---------------- final: BN2 + residual + ReLU --------------------------------
__global__ __launch_bounds__(256) void final_kernel(
    const float* __restrict__ x, const float* __restrict__ feat,
    float* __restrict__ y, int total4)
{
    int i = blockIdx.x * blockDim.x + threadIdx.x;
    if (i >= total4) return;
    float4 v = reinterpret_cast<const float4*>(x)[i];
    float4 f = reinterpret_cast<const float4*>(feat)[i];
    int c = (i * 4) & 63;
    float4 o;
    o.x = fmaxf(v.x * g_stats[c + 0] + g_stats[64 + c + 0] + f.x, 0.f);
    o.y = fmaxf(v.y * g_stats[c + 1] + g_stats[64 + c + 1] + f.y, 0.f);
    o.z = fmaxf(v.z * g_stats[c + 2] + g_stats[64 + c + 2] + f.z, 0.f);
    o.w = fmaxf(v.w * g_stats[c + 3] + g_stats[64 + c + 3] + f.w, 0.f);
    reinterpret_cast<float4*>(y)[i] = o;
}

// ---------------- launch ------------------------------------------------------
extern "C" void kernel_launch(void* const* d_in, const int* in_sizes, int n_in,
                              void* d_out, int out_size)
{
    const float* feat   = (const float*)d_in[0];
    const int*   nbr    = (const int*)  d_in[1];
    const float* valid  = (const float*)d_in[2];
    const float* W1     = (const float*)d_in[3];
    const float* gamma1 = (const float*)d_in[4];
    const float* beta1  = (const float*)d_in[5];
    const float* W2     = (const float*)d_in[6];
    const float* gamma2 = (const float*)d_in[7];
    const float* beta2  = (const float*)d_in[8];
    float* out = (float*)d_out;

    const int n = in_sizes[0] / CCH;
    const int nchunk = n * 8;
    const int total4 = (n * CCH) / 4;
    const int xb = (nchunk + 255) / 256;
    const int cenBlocks = (n + 127) / 128;

    float *buf1; uint4 *xhi, *xlo, *wt1, *wt2;
    cudaGetSymbolAddress((void**)&buf1, g_buf1);
    cudaGetSymbolAddress((void**)&xhi, g_xhi);
    cudaGetSymbolAddress((void**)&xlo, g_xlo);
    cudaGetSymbolAddress((void**)&wt1, g_wt1);
    cudaGetSymbolAddress((void**)&wt2, g_wt2);

    cudaFuncSetAttribute(fillcen_kernel, cudaFuncAttributeMaxDynamicSharedMemorySize, CEN_SMEM);
    cudaFuncSetAttribute(center_kernel, cudaFuncAttributeMaxDynamicSharedMemorySize, CEN_SMEM);
    cudaFuncSetAttribute(scatter_kernel, cudaFuncAttributeMaxDynamicSharedMemorySize, SC_SMEM);

    dim3 ewGrid((total4 + 255) / 256);
    dim3 bnGrid((nchunk + 255) / 256);

    // profiled launch index is 3 -> scatter_kernel (conv1)
    prepcount_kernel<<<54 + xb + FBLK, 256>>>(W1, W2, feat, valid, nchunk, xb, n); // 0
    scan_kernel<<<1, 1024>>>();                                                    // 1
    fillcen_kernel<<<FBLK + cenBlocks, 256, CEN_SMEM>>>(
        nbr, valid, xhi, xlo, wt1 + 13 * 1024, buf1, n);                           // 2
    scatter_kernel<<<SCGRID, 256, SC_SMEM>>>(xhi, xlo, wt1, buf1);                 // 3 <- profiled
    stats_kernel<<<SBLK, 256>>>(buf1, n);                                          // 4
    reduce_kernel<<<1, 512>>>(gamma1, beta1, n);                                   // 5
    bnrelu_kernel<<<bnGrid, 256>>>(buf1, nchunk);                                  // 6

    // conv2
    center_kernel<<<cenBlocks, 256, CEN_SMEM>>>(xhi, xlo, wt2 + 13 * 1024, buf1, n); // 7
    scatter_kernel<<<SCGRID, 256, SC_SMEM>>>(xhi, xlo, wt2, buf1);                   // 8
    stats_kernel<<<SBLK, 256>>>(buf1, n);                                            // 9
    reduce_kernel<<<1, 512>>>(gamma2, beta2, n);                                     // 10
    final_kernel<<<ewGrid, 256>>>(buf1, feat, out, total4);                          // 11
}

// round 14
// speedup vs baseline: 1.0138x; 1.0138x over previous
#include <cuda_runtime.h>
#include <cuda_bf16.h>
#include <cstdint>
#include <math.h>

#define NVOX   500000
#define CCH    64
#define KTAPS  27
#define SBLK   512
#define SCGRID 2048
#define FBLK   1664    // fill blocks (26 taps * 64)
#define MAXTIL 110000

// ---------------- static device scratch (no allocs allowed) -----------------
__device__ float g_buf1[(size_t)NVOX * CCH];      // conv out fp32 (pre-BN)
__device__ uint4 g_xhi[(size_t)NVOX * 8];         // bf16 hi features [n][64]
__device__ uint4 g_xlo[(size_t)NVOX * 8];         // bf16 lo features [n][64]
__device__ uint4 g_wt1[KTAPS * 1024];             // W1^T bf16 hi/lo, swizzled
__device__ uint4 g_wt2[KTAPS * 1024];             // W2^T bf16 hi/lo, swizzled
__device__ uint4 g_wf[(size_t)2 * 27 * 2 * 4 * 4 * 32];  // W in mma-fragment order
__device__ float g_part[SBLK * 128];
__device__ float g_stats[128];
__device__ int2  g_pairs[(size_t)NVOX * KTAPS];   // compacted (out,in), padded/128
__device__ int   g_bcnt[26 * 512];
__device__ int   g_boff[26 * 512];
__device__ int   g_meta[128];   // [0..26]=tile-base prefix (tb[26]=ntiles), [64+kk]=cnt
__device__ int   g_tmap[MAXTIL];                  // layer-major order -> tile id
__device__ int   g_ttap[MAXTIL];                  // layer-major order -> tap k

// ---------------- helpers ----------------------------------------------------
__device__ __forceinline__ uint32_t smem_u32(const void* p) {
    uint32_t a;
    asm("{ .reg .u64 t; cvta.to.shared.u64 t, %1; cvt.u32.u64 %0, t; }" : "=r"(a) : "l"(p));
    return a;
}
__device__ __host__ __forceinline__ uint32_t sw128(uint32_t off) {
    return off ^ ((off >> 3) & 0x70);
}
__device__ __forceinline__ void ldm_x4(uint32_t* r, uint32_t addr) {
    asm volatile("ldmatrix.sync.aligned.m8n8.x4.shared.b16 {%0,%1,%2,%3}, [%4];"
                 : "=r"(r[0]), "=r"(r[1]), "=r"(r[2]), "=r"(r[3]) : "r"(addr));
}
__device__ __forceinline__ void mma_bf16(float* d, const uint32_t* a,
                                         uint32_t b0, uint32_t b1) {
    asm volatile("mma.sync.aligned.m16n8k16.row.col.f32.bf16.bf16.f32 "
                 "{%0,%1,%2,%3}, {%4,%5,%6,%7}, {%8,%9}, {%0,%1,%2,%3};"
                 : "+f"(d[0]), "+f"(d[1]), "+f"(d[2]), "+f"(d[3])
                 : "r"(a[0]), "r"(a[1]), "r"(a[2]), "r"(a[3]), "r"(b0), "r"(b1));
}
__device__ __forceinline__ void cpa16(uint32_t dst, const void* src, uint32_t sz) {
    asm volatile("cp.async.cg.shared.global [%0], [%1], 16, %2;"
                 :: "r"(dst), "l"(src), "r"(sz) : "memory");
}
#define CP_COMMIT() asm volatile("cp.async.commit_group;" ::: "memory")
#define CP_WAIT0()  asm volatile("cp.async.wait_group 0;" ::: "memory")
__device__ __forceinline__ void redadd4(float* p, float x, float y, float z, float w) {
    asm volatile("red.global.v4.f32.add [%0], {%1,%2,%3,%4};"
                 :: "l"(p), "f"(x), "f"(y), "f"(z), "f"(w) : "memory");
}

// smem-W 3-pass MMA (used by center path; unchanged math)
__device__ __forceinline__ void tile_mma(
    uint32_t ab, uint32_t lb, uint32_t wh, uint32_t wl,
    const uint32_t aoff[4][2], const uint32_t boff[4][2], float acc[2][4][4])
{
    #pragma unroll
    for (int kc = 0; kc < 4; ++kc) {
        uint32_t ah[2][4], al[2][4], bh[2][4], bl[2][4];
        #pragma unroll
        for (int mi = 0; mi < 2; ++mi) {
            ldm_x4(ah[mi], ab + aoff[kc][mi]);
            ldm_x4(al[mi], lb + aoff[kc][mi]);
        }
        #pragma unroll
        for (int ni = 0; ni < 2; ++ni) {
            ldm_x4(bh[ni], wh + boff[kc][ni]);
            ldm_x4(bl[ni], wl + boff[kc][ni]);
        }
        #pragma unroll
        for (int mi = 0; mi < 2; ++mi)
            #pragma unroll
            for (int nt = 0; nt < 4; ++nt) {
                int ni = nt >> 1, s = nt & 1;
                mma_bf16(acc[mi][nt], ah[mi], bh[ni][s], bh[ni][s + 2]);
                mma_bf16(acc[mi][nt], ah[mi], bl[ni][s], bl[ni][s + 2]);
                mma_bf16(acc[mi][nt], al[mi], bh[ni][s], bh[ni][s + 2]);
            }
    }
}

// ---------------- split fp32 -> bf16 hi/lo ------------------------------------
__device__ __forceinline__ void split8(const float4& a, const float4& b,
                                       uint4& h, uint4& l)
{
    __nv_bfloat162 h0 = __floats2bfloat162_rn(a.x, a.y);
    __nv_bfloat162 h1 = __floats2bfloat162_rn(a.z, a.w);
    __nv_bfloat162 h2 = __floats2bfloat162_rn(b.x, b.y);
    __nv_bfloat162 h3 = __floats2bfloat162_rn(b.z, b.w);
    float2 f0 = __bfloat1622float2(h0), f1 = __bfloat1622float2(h1);
    float2 f2 = __bfloat1622float2(h2), f3 = __bfloat1622float2(h3);
    __nv_bfloat162 l0 = __floats2bfloat162_rn(a.x - f0.x, a.y - f0.y);
    __nv_bfloat162 l1 = __floats2bfloat162_rn(a.z - f1.x, a.w - f1.y);
    __nv_bfloat162 l2 = __floats2bfloat162_rn(b.x - f2.x, b.y - f2.y);
    __nv_bfloat162 l3 = __floats2bfloat162_rn(b.z - f3.x, b.w - f3.y);
    h = make_uint4(*(uint32_t*)&h0, *(uint32_t*)&h1, *(uint32_t*)&h2, *(uint32_t*)&h3);
    l = make_uint4(*(uint32_t*)&l0, *(uint32_t*)&l1, *(uint32_t*)&l2, *(uint32_t*)&l3);
}

// ---------------- fused prep+count ---------------------------------------------
__global__ __launch_bounds__(256) void prepcount_kernel(
    const float* __restrict__ W1, const float* __restrict__ W2,
    const float* __restrict__ x, const float* __restrict__ valid,
    int nchunk, int xb, int n)
{
    const int b = blockIdx.x;
    if (b < 54) {
        const int k = (b < 27) ? b : b - 27;
        const float* W = (b < 27) ? W1 : W2;
        uint4* wt = (b < 27) ? g_wt1 : g_wt2;
        char* dst = (char*)(wt + (size_t)k * 1024);
        for (int e = threadIdx.x; e < CCH * CCH; e += 256) {
            int ci = e >> 6, co = e & 63;
            float w = W[(size_t)k * CCH * CCH + e];
            __nv_bfloat16 h = __float2bfloat16(w);
            __nv_bfloat16 l = __float2bfloat16(w - __bfloat162float(h));
            uint32_t off = sw128((uint32_t)(co * 128 + ci * 2));
            *(__nv_bfloat16*)(dst + off) = h;
            *(__nv_bfloat16*)(dst + 8192 + off) = l;
        }
    } else if (b < 54 + xb) {
        int i = (b - 54) * 256 + threadIdx.x;
        if (i >= nchunk) return;
        const float4* x4 = (const float4*)x;
        float4 a = x4[2 * i], c = x4[2 * i + 1];
        uint4 h, l;
        split8(a, c, h, l);
        g_xhi[i] = h; g_xlo[i] = l;
    } else {
        const int cb = b - 54 - xb;
        const int kk = cb >> 6, bb = cb & 63;
        const int k = kk + (kk >= 13 ? 1 : 0);
        const int chunk = (n + 63) >> 6;
        const int r0 = bb * chunk, r1 = min(r0 + chunk, n);
        const int lane = threadIdx.x & 31, w = threadIdx.x >> 5;
        const int wc = (chunk + 7) >> 3;
        const int ws = r0 + w * wc, we = min(ws + wc, r1);
        const size_t kb = (size_t)k * n;
        int c = 0;
        for (int s = ws; s < we; s += 32) {
            int i = s + lane;
            bool v = (i < we) && (valid[kb + i] != 0.f);
            c += __popc(__ballot_sync(0xffffffffu, v));
        }
        if (lane == 0)
            g_bcnt[(size_t)cb * 8 + w] = c;
    }
}

// scan + build layer-major tile order map
__global__ __launch_bounds__(1024) void scan_kernel()
{
    __shared__ int stot[26];
    __shared__ int stb[27];
    const int tid = threadIdx.x, wid = tid >> 5, lane = tid & 31;
    int v[16], lexcl = 0;
    if (wid < 26) {
        const int base = wid * 512 + lane * 16;
        int s = 0;
        #pragma unroll
        for (int j = 0; j < 16; ++j) { v[j] = g_bcnt[base + j]; s += v[j]; }
        int p = s;
        #pragma unroll
        for (int d = 1; d < 32; d <<= 1) {
            int t = __shfl_up_sync(0xffffffffu, p, d);
            if (lane >= d) p += t;
        }
        lexcl = p - s;
        int tot = __shfl_sync(0xffffffffu, p, 31);
        if (lane == 0) stot[wid] = tot;
    }
    __syncthreads();
    if (tid == 0) {
        int tb = 0;
        for (int kk = 0; kk < 26; ++kk) {
            stb[kk] = tb;
            tb += (stot[kk] + 127) >> 7;
            g_meta[64 + kk] = stot[kk];
        }
        stb[26] = tb;
        for (int kk = 0; kk <= 26; ++kk) g_meta[kk] = stb[kk];
    }
    __syncthreads();
    if (wid < 26) {
        const int base = wid * 512 + lane * 16;
        int off = stb[wid] * 128 + lexcl;
        #pragma unroll
        for (int j = 0; j < 16; ++j) { g_boff[base + j] = off; off += v[j]; }
    }
    for (int kk = 0; kk < 26; ++kk) {
        const int tk = stb[kk + 1] - stb[kk];
        for (int j = tid; j < tk; j += 1024) {
            int pos = 0;
            #pragma unroll
            for (int q = 0; q < 26; ++q) {
                int tq = stb[q + 1] - stb[q];
                pos += min(tq, j);
                pos += (q < kk && tq > j) ? 1 : 0;
            }
            g_tmap[pos] = stb[kk] + j;
            g_ttap[pos] = kk + (kk >= 13 ? 1 : 0);
        }
    }
}

// ---------------- fused fill + center1 + wfrag ---------------------------------
// [0,FBLK): fill; [FBLK, FBLK+cenB): center1 GEMM; [FBLK+cenB, +108): W fragments
#define CEN_SMEM 49152
__global__ __launch_bounds__(256, 2) void fillcen_kernel(
    const int* __restrict__ nbr, const float* __restrict__ valid,
    const uint4* __restrict__ xhi, const uint4* __restrict__ xlo,
    const uint4* __restrict__ wtap, float* __restrict__ out, int n)
{
    const int cenB = (n + 127) >> 7;
    if (blockIdx.x < FBLK) {
        const int cb = blockIdx.x;
        const int kk = cb >> 6, bb = cb & 63;
        const int k = kk + (kk >= 13 ? 1 : 0);
        const int chunk = (n + 63) >> 6;
        const int r0 = bb * chunk, r1 = min(r0 + chunk, n);
        const int lane = threadIdx.x & 31, w = threadIdx.x >> 5;
        const int wc = (chunk + 7) >> 3;
        const int ws = r0 + w * wc, we = min(ws + wc, r1);
        const size_t kb = (size_t)k * n;

        int off = g_boff[(size_t)cb * 8 + w];
        for (int s = ws; s < we; s += 32) {
            int i = s + lane;
            bool v = (i < we) && (valid[kb + i] != 0.f);
            unsigned bal = __ballot_sync(0xffffffffu, v);
            if (v)
                g_pairs[off + __popc(bal & ((1u << lane) - 1u))] = make_int2(i, nbr[kb + i]);
            off += __popc(bal);
        }
        if (bb == 63) {
            const int cnt = g_meta[64 + kk];
            const int sbase = g_meta[kk] * 128;
            const int padded = (g_meta[kk + 1] - g_meta[kk]) * 128;
            for (int s = cnt + threadIdx.x; s < padded; s += 256)
                g_pairs[sbase + s] = make_int2(0, -1);
        }
        return;
    }

    extern __shared__ char smem[];
    const uint32_t sb = smem_u32(smem);
    const int tid = threadIdx.x, lane = tid & 31, wid = tid >> 5;

    if (blockIdx.x >= FBLK + cenB) {
        // ---- wfrag: replicate the scatter ldmatrix and store fragments ----
        const int task = blockIdx.x - FBLK - cenB;   // 0..107
        const int conv = task / 54;
        const int k = (task % 54) >> 1;
        const int g = task & 1;
        const uint4* wt = conv ? g_wt2 : g_wt1;
        uint4* s4 = (uint4*)smem;
        for (int e = tid; e < 1024; e += 256)
            s4[e] = wt[(size_t)k * 1024 + e];    // hi 512 u4, lo 512 u4 (linear copy)
        __syncthreads();
        if (wid == 0) {
            const uint32_t arow = lane & 15, agrp = (lane >> 4) * 16;
            const int nb0 = g * 32;
            uint4* dst = g_wf + ((size_t)((conv * 27 + k) * 2 + g) * 16) * 32;
            #pragma unroll
            for (int kc = 0; kc < 4; ++kc) {
                uint32_t bh[2][4], bl[2][4];
                #pragma unroll
                for (int ni = 0; ni < 2; ++ni) {
                    uint32_t off = sw128((uint32_t)((nb0 + ni * 16 + arow) * 128 + kc * 32) + agrp);
                    ldm_x4(bh[ni], sb + off);
                    ldm_x4(bl[ni], sb + 8192 + off);
                }
                uint4* d = dst + kc * 128;
                d[lane]       = make_uint4(bh[0][0], bh[0][1], bh[0][2], bh[0][3]);
                d[32 + lane]  = make_uint4(bh[1][0], bh[1][1], bh[1][2], bh[1][3]);
                d[64 + lane]  = make_uint4(bl[0][0], bl[0][1], bl[0][2], bl[0][3]);
                d[96 + lane]  = make_uint4(bl[1][0], bl[1][1], bl[1][2], bl[1][3]);
            }
        }
        return;
    }

    // ---- center1: dense identity-tap GEMM (smem W path) ----
    const int n0 = (blockIdx.x - FBLK) * 128;
    const int m0 = (wid & 3) * 32, nb0 = (wid >> 2) * 32;
    const int frow = tid >> 1, fhalf = tid & 1;

    const int g = n0 + frow;
    const uint32_t sz = (g < n) ? 16u : 0u;
    const int gc = min(g, n - 1);
    const char* sh = (const char*)(xhi + (size_t)gc * 8);
    const char* sl = (const char*)(xlo + (size_t)gc * 8);
    #pragma unroll
    for (int j = 0; j < 4; ++j) {
        int c = fhalf * 4 + j;
        uint32_t so = sw128((uint32_t)(frow * 128 + c * 16));
        cpa16(sb + so, sh + c * 16, sz);
        cpa16(sb + 16384 + so, sl + c * 16, sz);
    }
    const char* ws = (const char*)wtap;
    #pragma unroll
    for (int j = 0; j < 2; ++j) {
        int c = tid + j * 256;
        cpa16(sb + 32768 + c * 16, ws + c * 16, 16);
        cpa16(sb + 40960 + c * 16, ws + 8192 + c * 16, 16);
    }
    CP_COMMIT(); CP_WAIT0();
    __syncthreads();

    const uint32_t arow = lane & 15, agrp = (lane >> 4) * 16;
    uint32_t aoff[4][2], boff[4][2];
    #pragma unroll
    for (int kc = 0; kc < 4; ++kc) {
        #pragma unroll
        for (int mi = 0; mi < 2; ++mi)
            aoff[kc][mi] = sw128((uint32_t)((m0 + mi * 16 + arow) * 128 + kc * 32) + agrp);
        #pragma unroll
        for (int ni = 0; ni < 2; ++ni)
            boff[kc][ni] = sw128((uint32_t)((nb0 + ni * 16 + arow) * 128 + kc * 32) + agrp);
    }

    float acc[2][4][4];
    #pragma unroll
    for (int i = 0; i < 2; ++i)
        #pragma unroll
        for (int j = 0; j < 4; ++j)
            #pragma unroll
            for (int q = 0; q < 4; ++q) acc[i][j][q] = 0.f;

    tile_mma(sb, sb + 16384, sb + 32768, sb + 40960, aoff, boff, acc);

    const int rq = lane >> 2, cq = (lane & 3) * 2;
    #pragma unroll
    for (int mi = 0; mi < 2; ++mi)
        #pragma unroll
        for (int nt = 0; nt < 4; ++nt) {
            int col = nb0 + nt * 8 + cq;
            int r0 = n0 + m0 + mi * 16 + rq;
            if (r0 < n)
                *(float2*)(out + (size_t)r0 * CCH + col) = make_float2(acc[mi][nt][0], acc[mi][nt][1]);
            int r1 = r0 + 8;
            if (r1 < n)
                *(float2*)(out + (size_t)r1 * CCH + col) = make_float2(acc[mi][nt][2], acc[mi][nt][3]);
        }
}

// ---------------- standalone center (conv2) ------------------------------------
__global__ __launch_bounds__(256, 2) void center_kernel(
    const uint4* __restrict__ xhi, const uint4* __restrict__ xlo,
    const uint4* __restrict__ wtap, float* __restrict__ out, int n)
{
    extern __shared__ char smem[];
    const uint32_t sb = smem_u32(smem);
    const int tid = threadIdx.x, lane = tid & 31, wid = tid >> 5;
    const int n0 = blockIdx.x * 128;
    const int m0 = (wid & 3) * 32, nb0 = (wid >> 2) * 32;
    const int frow = tid >> 1, fhalf = tid & 1;

    const int g = n0 + frow;
    const uint32_t sz = (g < n) ? 16u : 0u;
    const int gc = min(g, n - 1);
    const char* sh = (const char*)(xhi + (size_t)gc * 8);
    const char* sl = (const char*)(xlo + (size_t)gc * 8);
    #pragma unroll
    for (int j = 0; j < 4; ++j) {
        int c = fhalf * 4 + j;
        uint32_t so = sw128((uint32_t)(frow * 128 + c * 16));
        cpa16(sb + so, sh + c * 16, sz);
        cpa16(sb + 16384 + so, sl + c * 16, sz);
    }
    const char* ws = (const char*)wtap;
    #pragma unroll
    for (int j = 0; j < 2; ++j) {
        int c = tid + j * 256;
        cpa16(sb + 32768 + c * 16, ws + c * 16, 16);
        cpa16(sb + 40960 + c * 16, ws + 8192 + c * 16, 16);
    }
    CP_COMMIT(); CP_WAIT0();
    __syncthreads();

    const uint32_t arow = lane & 15, agrp = (lane >> 4) * 16;
    uint32_t aoff[4][2], boff[4][2];
    #pragma unroll
    for (int kc = 0; kc < 4; ++kc) {
        #pragma unroll
        for (int mi = 0; mi < 2; ++mi)
            aoff[kc][mi] = sw128((uint32_t)((m0 + mi * 16 + arow) * 128 + kc * 32) + agrp);
        #pragma unroll
        for (int ni = 0; ni < 2; ++ni)
            boff[kc][ni] = sw128((uint32_t)((nb0 + ni * 16 + arow) * 128 + kc * 32) + agrp);
    }

    float acc[2][4][4];
    #pragma unroll
    for (int i = 0; i < 2; ++i)
        #pragma unroll
        for (int j = 0; j < 4; ++j)
            #pragma unroll
            for (int q = 0; q < 4; ++q) acc[i][j][q] = 0.f;

    tile_mma(sb, sb + 16384, sb + 32768, sb + 40960, aoff, boff, acc);

    const int rq = lane >> 2, cq = (lane & 3) * 2;
    #pragma unroll
    for (int mi = 0; mi < 2; ++mi)
        #pragma unroll
        for (int nt = 0; nt < 4; ++nt) {
            int col = nb0 + nt * 8 + cq;
            int r0 = n0 + m0 + mi * 16 + rq;
            if (r0 < n)
                *(float2*)(out + (size_t)r0 * CCH + col) = make_float2(acc[mi][nt][0], acc[mi][nt][1]);
            int r1 = r0 + 8;
            if (r1 < n)
                *(float2*)(out + (size_t)r1 * CCH + col) = make_float2(acc[mi][nt][2], acc[mi][nt][3]);
        }
}

// ---------------- scatter conv: layer-major, W via LDG fragments, occ 3 -------
#define SCA(s)     ((s) * 32768)            // A stage: hi 16KB + lo 16KB
#define SCP(ps)    (65536 + (ps) * 1024)    // pairs, 3 stages
#define SC_SMEM    68608

__global__ __launch_bounds__(256, 3) void scatter_kernel(
    const uint4* __restrict__ xhi, const uint4* __restrict__ xlo,
    const uint4* __restrict__ wf, float* __restrict__ out)
{
    extern __shared__ char smem[];
    const uint32_t sb = smem_u32(smem);
    const int tid = threadIdx.x, lane = tid & 31, wid = tid >> 5;
    const int m0 = (wid & 3) * 32, nb0 = (wid >> 2) * 32;
    const int wg = wid >> 2;               // W fragment n-group
    const int frow = tid >> 1, fhalf = tid & 1;

    const int ntiles = g_meta[26];
    int u = blockIdx.x;
    if (u >= ntiles) return;

    const uint32_t arow = lane & 15, agrp = (lane >> 4) * 16;
    uint32_t aoff[4][2];
    #pragma unroll
    for (int kc = 0; kc < 4; ++kc)
        #pragma unroll
        for (int mi = 0; mi < 2; ++mi)
            aoff[kc][mi] = sw128((uint32_t)((m0 + mi * 16 + arow) * 128 + kc * 32) + agrp);
    uint32_t so4[4];
    #pragma unroll
    for (int j = 0; j < 4; ++j)
        so4[j] = sw128((uint32_t)(frow * 128 + (fhalf * 4 + j) * 16));

    auto issuePairs = [&](int uu, int ps) {
        int tt = __ldg(&g_tmap[uu]);
        if (tid < 64)
            cpa16(sb + SCP(ps) + tid * 16,
                  (const char*)(g_pairs + (size_t)tt * 128) + tid * 16, 16);
    };
    auto issueA = [&](int s, int ps) {
        const int2* prs = (const int2*)(smem + SCP(ps));
        int in = prs[frow].y;
        uint32_t sz = (in >= 0) ? 16u : 0u;
        int ic = (in >= 0) ? in : 0;
        const char* sh = (const char*)(xhi + (size_t)ic * 8);
        const char* sl = (const char*)(xlo + (size_t)ic * 8);
        #pragma unroll
        for (int j = 0; j < 4; ++j) {
            int c = fhalf * 4 + j;
            cpa16(sb + SCA(s) + so4[j], sh + c * 16, sz);
            cpa16(sb + SCA(s) + 16384 + so4[j], sl + c * 16, sz);
        }
    };

    // prologue
    issuePairs(u, 0);
    if (u + SCGRID < ntiles) issuePairs(u + SCGRID, 1);
    CP_COMMIT(); CP_WAIT0();
    __syncthreads();
    issueA(0, 0);
    CP_COMMIT();

    const int rq = lane >> 2;
    const int cb = (lane & 2) * 2;
    const bool evn = !(lane & 1);
    int i = 0;
    while (true) {
        const int s = i & 1;
        const int ps = i % 3;
        const int k = __ldg(&g_ttap[u]);   // tap of current tile
        CP_WAIT0();
        __syncthreads();

        int un = u + SCGRID;
        bool hn = (un < ntiles);
        if (hn) {
            issueA(s ^ 1, (i + 1) % 3);
            int un2 = un + SCGRID;
            if (un2 < ntiles) issuePairs(un2, (i + 2) % 3);
            CP_COMMIT();
        }

        float acc[2][4][4];
        #pragma unroll
        for (int a = 0; a < 2; ++a)
            #pragma unroll
            for (int b = 0; b < 4; ++b)
                #pragma unroll
                for (int q = 0; q < 4; ++q) acc[a][b][q] = 0.f;

        const uint32_t ab = sb + SCA(s);
        const uint32_t lb = ab + 16384;
        const uint4* wfk = wf + ((size_t)(k * 2 + wg) * 16) * 32;
        #pragma unroll
        for (int kc = 0; kc < 4; ++kc) {
            uint32_t ah[2][4], al[2][4];
            #pragma unroll
            for (int mi = 0; mi < 2; ++mi) {
                ldm_x4(ah[mi], ab + aoff[kc][mi]);
                ldm_x4(al[mi], lb + aoff[kc][mi]);
            }
            const uint4* p = wfk + kc * 128;
            uint4 h0 = __ldg(p + lane);
            uint4 h1 = __ldg(p + 32 + lane);
            uint4 l0 = __ldg(p + 64 + lane);
            uint4 l1 = __ldg(p + 96 + lane);
            uint32_t bh[2][4] = {{h0.x, h0.y, h0.z, h0.w}, {h1.x, h1.y, h1.z, h1.w}};
            uint32_t bl[2][4] = {{l0.x, l0.y, l0.z, l0.w}, {l1.x, l1.y, l1.z, l1.w}};
            #pragma unroll
            for (int mi = 0; mi < 2; ++mi)
                #pragma unroll
                for (int nt = 0; nt < 4; ++nt) {
                    int ni = nt >> 1, ss = nt & 1;
                    mma_bf16(acc[mi][nt], ah[mi], bh[ni][ss], bh[ni][ss + 2]);
                    mma_bf16(acc[mi][nt], ah[mi], bl[ni][ss], bl[ni][ss + 2]);
                    mma_bf16(acc[mi][nt], al[mi], bh[ni][ss], bh[ni][ss + 2]);
                }
        }

        const int2* prs = (const int2*)(smem + SCP(ps));
        #pragma unroll
        for (int mi = 0; mi < 2; ++mi) {
            int r = m0 + mi * 16 + rq;
            int2 p0 = prs[r];
            int2 p1 = prs[r + 8];
            float* o0 = out + (size_t)p0.x * CCH;
            float* o1 = out + (size_t)p1.x * CCH;
            #pragma unroll
            for (int nt = 0; nt < 4; ++nt) {
                float a0 = acc[mi][nt][0], a1 = acc[mi][nt][1];
                float a2 = acc[mi][nt][2], a3 = acc[mi][nt][3];
                float b0 = __shfl_xor_sync(0xffffffffu, a0, 1);
                float b1 = __shfl_xor_sync(0xffffffffu, a1, 1);
                float b2 = __shfl_xor_sync(0xffffffffu, a2, 1);
                float b3 = __shfl_xor_sync(0xffffffffu, a3, 1);
                int col = nb0 + nt * 8 + cb;
                if (evn) {
                    if (p0.y >= 0) redadd4(o0 + col, a0, a1, b0, b1);
                } else {
                    if (p1.y >= 0) redadd4(o1 + col, b2, b3, a2, a3);
                }
            }
        }
        if (!hn) break;
        u = un;
        ++i;
    }
}

// ---------------- bnrelu: BN + ReLU fused, writes bf16 hi/lo -------------------
__global__ __launch_bounds__(256) void bnrelu_kernel(const float* __restrict__ x, int nchunk)
{
    int i = blockIdx.x * blockDim.x + threadIdx.x;
    if (i >= nchunk) return;
    const float4* x4 = (const float4*)x;
    float4 a = x4[2 * i], b = x4[2 * i + 1];
    int c = (i * 8) & 63;
    a.x = fmaxf(a.x * g_stats[c + 0] + g_stats[64 + c + 0], 0.f);
    a.y = fmaxf(a.y * g_stats[c + 1] + g_stats[64 + c + 1], 0.f);
    a.z = fmaxf(a.z * g_stats[c + 2] + g_stats[64 + c + 2], 0.f);
    a.w = fmaxf(a.w * g_stats[c + 3] + g_stats[64 + c + 3], 0.f);
    b.x = fmaxf(b.x * g_stats[c + 4] + g_stats[64 + c + 4], 0.f);
    b.y = fmaxf(b.y * g_stats[c + 5] + g_stats[64 + c + 5], 0.f);
    b.z = fmaxf(b.z * g_stats[c + 6] + g_stats[64 + c + 6], 0.f);
    b.w = fmaxf(b.w * g_stats[c + 7] + g_stats[64 + c + 7], 0.f);
    uint4 h, l;
    split8(a, b, h, l);
    g_xhi[i] = h; g_xlo[i] = l;
}

// ---------------- BN stats (deterministic) ------------------------------------
__global__ __launch_bounds__(256) void stats_kernel(const float* __restrict__ buf, int n)
{
    __shared__ float s[4][128];
    const int tid = threadIdx.x, lane = tid & 63, grp = tid >> 6;
    const int chunk = (n + SBLK - 1) / SBLK;
    const int r0 = blockIdx.x * chunk;
    const int r1 = min(r0 + chunk, n);
    float sm = 0.f, sq = 0.f;
    for (int r = r0 + grp; r < r1; r += 4) {
        float v = buf[(size_t)r * CCH + lane];
        sm += v; sq += v * v;
    }
    s[grp][lane] = sm; s[grp][64 + lane] = sq;
    __syncthreads();
    if (tid < 128)
        g_part[(size_t)blockIdx.x * 128 + tid] = s[0][tid] + s[1][tid] + s[2][tid] + s[3][tid];
}

__global__ __launch_bounds__(512) void reduce_kernel(
    const float* __restrict__ gamma, const float* __restrict__ beta, int n)
{
    __shared__ float s[4][128];
    const int tid = threadIdx.x, col = tid & 127, grp = tid >> 7;
    float acc = 0.f;
    for (int b = grp; b < SBLK; b += 4) acc += g_part[(size_t)b * 128 + col];
    s[grp][col] = acc;
    __syncthreads();
    if (tid < 128) s[0][tid] = s[0][tid] + s[1][tid] + s[2][tid] + s[3][tid];
    __syncthreads();
    if (tid < 64) {
        float inv_n = 1.0f / (float)n;
        float mean = s[0][tid] * inv_n;
        float var = s[0][64 + tid] * inv_n - mean * mean;
        float scale = gamma[tid] * rsqrtf(var + 1e-5f);
        g_stats[tid] = scale;
        g_stats[64 + tid] = beta[tid] - mean * scale;
    }
}

// ---------------- final: BN2 + residual + ReLU --------------------------------
__global__ __launch_bounds__(256) void final_kernel(
    const float* __restrict__ x, const float* __restrict__ feat,
    float* __restrict__ y, int total4)
{
    int i = blockIdx.x * blockDim.x + threadIdx.x;
    if (i >= total4) return;
    float4 v = reinterpret_cast<const float4*>(x)[i];
    float4 f = reinterpret_cast<const float4*>(feat)[i];
    int c = (i * 4) & 63;
    float4 o;
    o.x = fmaxf(v.x * g_stats[c + 0] + g_stats[64 + c + 0] + f.x, 0.f);
    o.y = fmaxf(v.y * g_stats[c + 1] + g_stats[64 + c + 1] + f.y, 0.f);
    o.z = fmaxf(v.z * g_stats[c + 2] + g_stats[64 + c + 2] + f.z, 0.f);
    o.w = fmaxf(v.w * g_stats[c + 3] + g_stats[64 + c + 3] + f.w, 0.f);
    reinterpret_cast<float4*>(y)[i] = o;
}

// ---------------- launch ------------------------------------------------------
extern "C" void kernel_launch(void* const* d_in, const int* in_sizes, int n_in,
                              void* d_out, int out_size)
{
    const float* feat   = (const float*)d_in[0];
    const int*   nbr    = (const int*)  d_in[1];
    const float* valid  = (const float*)d_in[2];
    const float* W1     = (const float*)d_in[3];
    const float* gamma1 = (const float*)d_in[4];
    const float* beta1  = (const float*)d_in[5];
    const float* W2     = (const float*)d_in[6];
    const float* gamma2 = (const float*)d_in[7];
    const float* beta2  = (const float*)d_in[8];
    float* out = (float*)d_out;

    const int n = in_sizes[0] / CCH;
    const int nchunk = n * 8;
    const int total4 = (n * CCH) / 4;
    const int xb = (nchunk + 255) / 256;
    const int cenBlocks = (n + 127) / 128;

    float *buf1; uint4 *xhi, *xlo, *wt1, *wt2, *wfb;
    cudaGetSymbolAddress((void**)&buf1, g_buf1);
    cudaGetSymbolAddress((void**)&xhi, g_xhi);
    cudaGetSymbolAddress((void**)&xlo, g_xlo);
    cudaGetSymbolAddress((void**)&wt1, g_wt1);
    cudaGetSymbolAddress((void**)&wt2, g_wt2);
    cudaGetSymbolAddress((void**)&wfb, g_wf);

    cudaFuncSetAttribute(fillcen_kernel, cudaFuncAttributeMaxDynamicSharedMemorySize, CEN_SMEM);
    cudaFuncSetAttribute(center_kernel, cudaFuncAttributeMaxDynamicSharedMemorySize, CEN_SMEM);
    cudaFuncSetAttribute(scatter_kernel, cudaFuncAttributeMaxDynamicSharedMemorySize, SC_SMEM);

    dim3 ewGrid((total4 + 255) / 256);
    dim3 bnGrid((nchunk + 255) / 256);

    // profiled launch index is 3 -> scatter_kernel (conv1)
    prepcount_kernel<<<54 + xb + FBLK, 256>>>(W1, W2, feat, valid, nchunk, xb, n); // 0
    scan_kernel<<<1, 1024>>>();                                                    // 1
    fillcen_kernel<<<FBLK + cenBlocks + 108, 256, CEN_SMEM>>>(
        nbr, valid, xhi, xlo, wt1 + 13 * 1024, buf1, n);                           // 2
    scatter_kernel<<<SCGRID, 256, SC_SMEM>>>(xhi, xlo, wfb, buf1);                 // 3 <- profiled
    stats_kernel<<<SBLK, 256>>>(buf1, n);                                          // 4
    reduce_kernel<<<1, 512>>>(gamma1, beta1, n);                                   // 5
    bnrelu_kernel<<<bnGrid, 256>>>(buf1, nchunk);                                  // 6

    // conv2
    center_kernel<<<cenBlocks, 256, CEN_SMEM>>>(xhi, xlo, wt2 + 13 * 1024, buf1, n); // 7
    scatter_kernel<<<SCGRID, 256, SC_SMEM>>>(xhi, xlo, wfb + 27 * 2 * 16 * 32, buf1); // 8
    stats_kernel<<<SBLK, 256>>>(buf1, n);                                            // 9
    reduce_kernel<<<1, 512>>>(gamma2, beta2, n);                                     // 10
    final_kernel<<<ewGrid, 256>>>(buf1, feat, out, total4);                          // 11
}

// round 15
// speedup vs baseline: 1.1843x; 1.1682x over previous
#include <cuda_runtime.h>
#include <cuda_fp16.h>
#include <cstdint>
#include <math.h>

#define NVOX   500000
#define CCH    64
#define KTAPS  27
#define SBLK   512
#define SCGRID 2048
#define FBLK   1664
#define MAXTIL 110000

// ---------------- static device scratch (no allocs allowed) -----------------
__device__ float g_buf1[(size_t)NVOX * CCH];      // conv out fp32 (pre-BN)
__device__ uint4 g_xh[(size_t)NVOX * 8];          // fp16 features [n][64]
__device__ uint4 g_wt1[KTAPS * 1024];             // W1^T fp16 hi/lo, swizzled
__device__ uint4 g_wt2[KTAPS * 1024];             // W2^T fp16 hi/lo, swizzled
__device__ uint4 g_wf[(size_t)2 * 27 * 2 * 4 * 4 * 32];  // W mma fragments
__device__ float g_part[SBLK * 128];
__device__ float g_stats[128];
__device__ int2  g_pairs[(size_t)NVOX * KTAPS];   // compacted (out,in), padded/128
__device__ int   g_bcnt[26 * 512];
__device__ int   g_boff[26 * 512];
__device__ int   g_meta[128];
__device__ int   g_tmap[MAXTIL];
__device__ int   g_ttap[MAXTIL];

// ---------------- helpers ----------------------------------------------------
__device__ __forceinline__ uint32_t smem_u32(const void* p) {
    uint32_t a;
    asm("{ .reg .u64 t; cvta.to.shared.u64 t, %1; cvt.u32.u64 %0, t; }" : "=r"(a) : "l"(p));
    return a;
}
__device__ __host__ __forceinline__ uint32_t sw128(uint32_t off) {
    return off ^ ((off >> 3) & 0x70);
}
__device__ __forceinline__ void ldm_x4(uint32_t* r, uint32_t addr) {
    asm volatile("ldmatrix.sync.aligned.m8n8.x4.shared.b16 {%0,%1,%2,%3}, [%4];"
                 : "=r"(r[0]), "=r"(r[1]), "=r"(r[2]), "=r"(r[3]) : "r"(addr));
}
__device__ __forceinline__ void mma_f16(float* d, const uint32_t* a,
                                        uint32_t b0, uint32_t b1) {
    asm volatile("mma.sync.aligned.m16n8k16.row.col.f32.f16.f16.f32 "
                 "{%0,%1,%2,%3}, {%4,%5,%6,%7}, {%8,%9}, {%0,%1,%2,%3};"
                 : "+f"(d[0]), "+f"(d[1]), "+f"(d[2]), "+f"(d[3])
                 : "r"(a[0]), "r"(a[1]), "r"(a[2]), "r"(a[3]), "r"(b0), "r"(b1));
}
__device__ __forceinline__ void cpa16(uint32_t dst, const void* src, uint32_t sz) {
    asm volatile("cp.async.cg.shared.global [%0], [%1], 16, %2;"
                 :: "r"(dst), "l"(src), "r"(sz) : "memory");
}
#define CP_COMMIT() asm volatile("cp.async.commit_group;" ::: "memory")
#define CP_WAIT0()  asm volatile("cp.async.wait_group 0;" ::: "memory")
__device__ __forceinline__ void redadd4(float* p, float x, float y, float z, float w) {
    asm volatile("red.global.v4.f32.add [%0], {%1,%2,%3,%4};"
                 :: "l"(p), "f"(x), "f"(y), "f"(z), "f"(w) : "memory");
}

// 8 floats -> 8 fp16 packed in one uint4
__device__ __forceinline__ uint4 cvt8(const float4& a, const float4& b)
{
    __half2 h0 = __floats2half2_rn(a.x, a.y);
    __half2 h1 = __floats2half2_rn(a.z, a.w);
    __half2 h2 = __floats2half2_rn(b.x, b.y);
    __half2 h3 = __floats2half2_rn(b.z, b.w);
    return make_uint4(*(uint32_t*)&h0, *(uint32_t*)&h1, *(uint32_t*)&h2, *(uint32_t*)&h3);
}

// 2-pass MMA over one 128x64x64 tile: A fp16 in smem, W hi/lo fp16 in smem
__device__ __forceinline__ void tile_mma2(
    uint32_t ab, uint32_t wh, uint32_t wl,
    const uint32_t aoff[4][2], const uint32_t boff[4][2], float acc[2][4][4])
{
    #pragma unroll
    for (int kc = 0; kc < 4; ++kc) {
        uint32_t ah[2][4], bh[2][4], bl[2][4];
        #pragma unroll
        for (int mi = 0; mi < 2; ++mi)
            ldm_x4(ah[mi], ab + aoff[kc][mi]);
        #pragma unroll
        for (int ni = 0; ni < 2; ++ni) {
            ldm_x4(bh[ni], wh + boff[kc][ni]);
            ldm_x4(bl[ni], wl + boff[kc][ni]);
        }
        #pragma unroll
        for (int mi = 0; mi < 2; ++mi)
            #pragma unroll
            for (int nt = 0; nt < 4; ++nt) {
                int ni = nt >> 1, s = nt & 1;
                mma_f16(acc[mi][nt], ah[mi], bh[ni][s], bh[ni][s + 2]);
                mma_f16(acc[mi][nt], ah[mi], bl[ni][s], bl[ni][s + 2]);
            }
    }
}

// ---------------- fused prep+count ---------------------------------------------
__global__ __launch_bounds__(256) void prepcount_kernel(
    const float* __restrict__ W1, const float* __restrict__ W2,
    const float* __restrict__ x, const float* __restrict__ valid,
    int nchunk, int xb, int n)
{
    const int b = blockIdx.x;
    if (b < 54) {
        const int k = (b < 27) ? b : b - 27;
        const float* W = (b < 27) ? W1 : W2;
        uint4* wt = (b < 27) ? g_wt1 : g_wt2;
        char* dst = (char*)(wt + (size_t)k * 1024);
        for (int e = threadIdx.x; e < CCH * CCH; e += 256) {
            int ci = e >> 6, co = e & 63;
            float w = W[(size_t)k * CCH * CCH + e];
            __half h = __float2half_rn(w);
            __half l = __float2half_rn(w - __half2float(h));
            uint32_t off = sw128((uint32_t)(co * 128 + ci * 2));
            *(__half*)(dst + off) = h;
            *(__half*)(dst + 8192 + off) = l;
        }
    } else if (b < 54 + xb) {
        int i = (b - 54) * 256 + threadIdx.x;
        if (i >= nchunk) return;
        const float4* x4 = (const float4*)x;
        g_xh[i] = cvt8(x4[2 * i], x4[2 * i + 1]);
    } else {
        const int cb = b - 54 - xb;
        const int kk = cb >> 6, bb = cb & 63;
        const int k = kk + (kk >= 13 ? 1 : 0);
        const int chunk = (n + 63) >> 6;
        const int r0 = bb * chunk, r1 = min(r0 + chunk, n);
        const int lane = threadIdx.x & 31, w = threadIdx.x >> 5;
        const int wc = (chunk + 7) >> 3;
        const int ws = r0 + w * wc, we = min(ws + wc, r1);
        const size_t kb = (size_t)k * n;
        int c = 0;
        for (int s = ws; s < we; s += 32) {
            int i = s + lane;
            bool v = (i < we) && (valid[kb + i] != 0.f);
            c += __popc(__ballot_sync(0xffffffffu, v));
        }
        if (lane == 0)
            g_bcnt[(size_t)cb * 8 + w] = c;
    }
}

// scan + layer-major map
__global__ __launch_bounds__(1024) void scan_kernel()
{
    __shared__ int stot[26];
    __shared__ int stb[27];
    const int tid = threadIdx.x, wid = tid >> 5, lane = tid & 31;
    int v[16], lexcl = 0;
    if (wid < 26) {
        const int base = wid * 512 + lane * 16;
        int s = 0;
        #pragma unroll
        for (int j = 0; j < 16; ++j) { v[j] = g_bcnt[base + j]; s += v[j]; }
        int p = s;
        #pragma unroll
        for (int d = 1; d < 32; d <<= 1) {
            int t = __shfl_up_sync(0xffffffffu, p, d);
            if (lane >= d) p += t;
        }
        lexcl = p - s;
        int tot = __shfl_sync(0xffffffffu, p, 31);
        if (lane == 0) stot[wid] = tot;
    }
    __syncthreads();
    if (tid == 0) {
        int tb = 0;
        for (int kk = 0; kk < 26; ++kk) {
            stb[kk] = tb;
            tb += (stot[kk] + 127) >> 7;
            g_meta[64 + kk] = stot[kk];
        }
        stb[26] = tb;
        for (int kk = 0; kk <= 26; ++kk) g_meta[kk] = stb[kk];
    }
    __syncthreads();
    if (wid < 26) {
        const int base = wid * 512 + lane * 16;
        int off = stb[wid] * 128 + lexcl;
        #pragma unroll
        for (int j = 0; j < 16; ++j) { g_boff[base + j] = off; off += v[j]; }
    }
    for (int kk = 0; kk < 26; ++kk) {
        const int tk = stb[kk + 1] - stb[kk];
        for (int j = tid; j < tk; j += 1024) {
            int pos = 0;
            #pragma unroll
            for (int q = 0; q < 26; ++q) {
                int tq = stb[q + 1] - stb[q];
                pos += min(tq, j);
                pos += (q < kk && tq > j) ? 1 : 0;
            }
            g_tmap[pos] = stb[kk] + j;
            g_ttap[pos] = kk + (kk >= 13 ? 1 : 0);
        }
    }
}

// ---------------- fused fill + center1 + wfrag ---------------------------------
#define CEN_SMEM 33024
__global__ __launch_bounds__(256, 2) void fillcen_kernel(
    const int* __restrict__ nbr, const float* __restrict__ valid,
    const uint4* __restrict__ xh, const uint4* __restrict__ wtap,
    float* __restrict__ out, int n)
{
    const int cenB = (n + 127) >> 7;
    if (blockIdx.x < FBLK) {
        const int cb = blockIdx.x;
        const int kk = cb >> 6, bb = cb & 63;
        const int k = kk + (kk >= 13 ? 1 : 0);
        const int chunk = (n + 63) >> 6;
        const int r0 = bb * chunk, r1 = min(r0 + chunk, n);
        const int lane = threadIdx.x & 31, w = threadIdx.x >> 5;
        const int wc = (chunk + 7) >> 3;
        const int ws = r0 + w * wc, we = min(ws + wc, r1);
        const size_t kb = (size_t)k * n;

        int off = g_boff[(size_t)cb * 8 + w];
        for (int s = ws; s < we; s += 32) {
            int i = s + lane;
            bool v = (i < we) && (valid[kb + i] != 0.f);
            unsigned bal = __ballot_sync(0xffffffffu, v);
            if (v)
                g_pairs[off + __popc(bal & ((1u << lane) - 1u))] = make_int2(i, nbr[kb + i]);
            off += __popc(bal);
        }
        if (bb == 63) {
            const int cnt = g_meta[64 + kk];
            const int sbase = g_meta[kk] * 128;
            const int padded = (g_meta[kk + 1] - g_meta[kk]) * 128;
            for (int s = cnt + threadIdx.x; s < padded; s += 256)
                g_pairs[sbase + s] = make_int2(0, -1);
        }
        return;
    }

    extern __shared__ char smem[];
    const uint32_t sb = smem_u32(smem);
    const int tid = threadIdx.x, lane = tid & 31, wid = tid >> 5;

    if (blockIdx.x >= FBLK + cenB) {
        // wfrag: store W mma fragments (fp16 hi/lo)
        const int task = blockIdx.x - FBLK - cenB;   // 0..107
        const int conv = task / 54;
        const int k = (task % 54) >> 1;
        const int g = task & 1;
        const uint4* wt = conv ? g_wt2 : g_wt1;
        uint4* s4 = (uint4*)smem;
        for (int e = tid; e < 1024; e += 256)
            s4[e] = wt[(size_t)k * 1024 + e];
        __syncthreads();
        if (wid == 0) {
            const uint32_t arow = lane & 15, agrp = (lane >> 4) * 16;
            const int nb0 = g * 32;
            uint4* dst = g_wf + ((size_t)((conv * 27 + k) * 2 + g) * 16) * 32;
            #pragma unroll
            for (int kc = 0; kc < 4; ++kc) {
                uint32_t bh[2][4], bl[2][4];
                #pragma unroll
                for (int ni = 0; ni < 2; ++ni) {
                    uint32_t off = sw128((uint32_t)((nb0 + ni * 16 + arow) * 128 + kc * 32) + agrp);
                    ldm_x4(bh[ni], sb + off);
                    ldm_x4(bl[ni], sb + 8192 + off);
                }
                uint4* d = dst + kc * 128;
                d[lane]      = make_uint4(bh[0][0], bh[0][1], bh[0][2], bh[0][3]);
                d[32 + lane] = make_uint4(bh[1][0], bh[1][1], bh[1][2], bh[1][3]);
                d[64 + lane] = make_uint4(bl[0][0], bl[0][1], bl[0][2], bl[0][3]);
                d[96 + lane] = make_uint4(bl[1][0], bl[1][1], bl[1][2], bl[1][3]);
            }
        }
        return;
    }

    // center1: dense identity-tap GEMM, 2-pass fp16
    const int n0 = (blockIdx.x - FBLK) * 128;
    const int m0 = (wid & 3) * 32, nb0 = (wid >> 2) * 32;
    const int frow = tid >> 1, fhalf = tid & 1;

    const int g = n0 + frow;
    const uint32_t sz = (g < n) ? 16u : 0u;
    const int gc = min(g, n - 1);
    const char* sh = (const char*)(xh + (size_t)gc * 8);
    #pragma unroll
    for (int j = 0; j < 4; ++j) {
        int c = fhalf * 4 + j;
        cpa16(sb + sw128((uint32_t)(frow * 128 + c * 16)), sh + c * 16, sz);
    }
    const char* ws = (const char*)wtap;
    #pragma unroll
    for (int j = 0; j < 4; ++j) {
        int c = tid + j * 256;          // 0..1023: hi 512 chunks then lo 512
        cpa16(sb + 16384 + c * 16, ws + c * 16, 16);
    }
    CP_COMMIT(); CP_WAIT0();
    __syncthreads();

    const uint32_t arow = lane & 15, agrp = (lane >> 4) * 16;
    uint32_t aoff[4][2], boff[4][2];
    #pragma unroll
    for (int kc = 0; kc < 4; ++kc) {
        #pragma unroll
        for (int mi = 0; mi < 2; ++mi)
            aoff[kc][mi] = sw128((uint32_t)((m0 + mi * 16 + arow) * 128 + kc * 32) + agrp);
        #pragma unroll
        for (int ni = 0; ni < 2; ++ni)
            boff[kc][ni] = sw128((uint32_t)((nb0 + ni * 16 + arow) * 128 + kc * 32) + agrp);
    }

    float acc[2][4][4];
    #pragma unroll
    for (int i = 0; i < 2; ++i)
        #pragma unroll
        for (int j = 0; j < 4; ++j)
            #pragma unroll
            for (int q = 0; q < 4; ++q) acc[i][j][q] = 0.f;

    tile_mma2(sb, sb + 16384, sb + 24576, aoff, boff, acc);

    const int rq = lane >> 2, cq = (lane & 3) * 2;
    #pragma unroll
    for (int mi = 0; mi < 2; ++mi)
        #pragma unroll
        for (int nt = 0; nt < 4; ++nt) {
            int col = nb0 + nt * 8 + cq;
            int r0 = n0 + m0 + mi * 16 + rq;
            if (r0 < n)
                *(float2*)(out + (size_t)r0 * CCH + col) = make_float2(acc[mi][nt][0], acc[mi][nt][1]);
            int r1 = r0 + 8;
            if (r1 < n)
                *(float2*)(out + (size_t)r1 * CCH + col) = make_float2(acc[mi][nt][2], acc[mi][nt][3]);
        }
}

// ---------------- standalone center (conv2) ------------------------------------
__global__ __launch_bounds__(256, 2) void center_kernel(
    const uint4* __restrict__ xh, const uint4* __restrict__ wtap,
    float* __restrict__ out, int n)
{
    extern __shared__ char smem[];
    const uint32_t sb = smem_u32(smem);
    const int tid = threadIdx.x, lane = tid & 31, wid = tid >> 5;
    const int n0 = blockIdx.x * 128;
    const int m0 = (wid & 3) * 32, nb0 = (wid >> 2) * 32;
    const int frow = tid >> 1, fhalf = tid & 1;

    const int g = n0 + frow;
    const uint32_t sz = (g < n) ? 16u : 0u;
    const int gc = min(g, n - 1);
    const char* sh = (const char*)(xh + (size_t)gc * 8);
    #pragma unroll
    for (int j = 0; j < 4; ++j) {
        int c = fhalf * 4 + j;
        cpa16(sb + sw128((uint32_t)(frow * 128 + c * 16)), sh + c * 16, sz);
    }
    const char* ws = (const char*)wtap;
    #pragma unroll
    for (int j = 0; j < 4; ++j) {
        int c = tid + j * 256;
        cpa16(sb + 16384 + c * 16, ws + c * 16, 16);
    }
    CP_COMMIT(); CP_WAIT0();
    __syncthreads();

    const uint32_t arow = lane & 15, agrp = (lane >> 4) * 16;
    uint32_t aoff[4][2], boff[4][2];
    #pragma unroll
    for (int kc = 0; kc < 4; ++kc) {
        #pragma unroll
        for (int mi = 0; mi < 2; ++mi)
            aoff[kc][mi] = sw128((uint32_t)((m0 + mi * 16 + arow) * 128 + kc * 32) + agrp);
        #pragma unroll
        for (int ni = 0; ni < 2; ++ni)
            boff[kc][ni] = sw128((uint32_t)((nb0 + ni * 16 + arow) * 128 + kc * 32) + agrp);
    }

    float acc[2][4][4];
    #pragma unroll
    for (int i = 0; i < 2; ++i)
        #pragma unroll
        for (int j = 0; j < 4; ++j)
            #pragma unroll
            for (int q = 0; q < 4; ++q) acc[i][j][q] = 0.f;

    tile_mma2(sb, sb + 16384, sb + 24576, aoff, boff, acc);

    const int rq = lane >> 2, cq = (lane & 3) * 2;
    #pragma unroll
    for (int mi = 0; mi < 2; ++mi)
        #pragma unroll
        for (int nt = 0; nt < 4; ++nt) {
            int col = nb0 + nt * 8 + cq;
            int r0 = n0 + m0 + mi * 16 + rq;
            if (r0 < n)
                *(float2*)(out + (size_t)r0 * CCH + col) = make_float2(acc[mi][nt][0], acc[mi][nt][1]);
            int r1 = r0 + 8;
            if (r1 < n)
                *(float2*)(out + (size_t)r1 * CCH + col) = make_float2(acc[mi][nt][2], acc[mi][nt][3]);
        }
}

// ---------------- scatter conv: fp16 2-pass, layer-major, W LDG fragments ------
#define SCA(s)     ((s) * 16384)            // A stage fp16: 16KB
#define SCP(ps)    (32768 + (ps) * 1024)    // pairs, 3 stages
#define SC_SMEM    35840

__global__ __launch_bounds__(256, 3) void scatter_kernel(
    const uint4* __restrict__ xh, const uint4* __restrict__ wf,
    float* __restrict__ out)
{
    extern __shared__ char smem[];
    const uint32_t sb = smem_u32(smem);
    const int tid = threadIdx.x, lane = tid & 31, wid = tid >> 5;
    const int m0 = (wid & 3) * 32, nb0 = (wid >> 2) * 32;
    const int wg = wid >> 2;
    const int frow = tid >> 1, fhalf = tid & 1;

    const int ntiles = g_meta[26];
    int u = blockIdx.x;
    if (u >= ntiles) return;

    const uint32_t arow = lane & 15, agrp = (lane >> 4) * 16;
    uint32_t aoff[4][2];
    #pragma unroll
    for (int kc = 0; kc < 4; ++kc)
        #pragma unroll
        for (int mi = 0; mi < 2; ++mi)
            aoff[kc][mi] = sw128((uint32_t)((m0 + mi * 16 + arow) * 128 + kc * 32) + agrp);
    uint32_t so4[4];
    #pragma unroll
    for (int j = 0; j < 4; ++j)
        so4[j] = sw128((uint32_t)(frow * 128 + (fhalf * 4 + j) * 16));

    auto issuePairs = [&](int uu, int ps) {
        int tt = __ldg(&g_tmap[uu]);
        if (tid < 64)
            cpa16(sb + SCP(ps) + tid * 16,
                  (const char*)(g_pairs + (size_t)tt * 128) + tid * 16, 16);
    };
    auto issueA = [&](int s, int ps) {
        const int2* prs = (const int2*)(smem + SCP(ps));
        int in = prs[frow].y;
        uint32_t sz = (in >= 0) ? 16u : 0u;
        int ic = (in >= 0) ? in : 0;
        const char* sh = (const char*)(xh + (size_t)ic * 8);
        #pragma unroll
        for (int j = 0; j < 4; ++j)
            cpa16(sb + SCA(s) + so4[j], sh + (fhalf * 4 + j) * 16, sz);
    };

    // prologue
    issuePairs(u, 0);
    if (u + SCGRID < ntiles) issuePairs(u + SCGRID, 1);
    CP_COMMIT(); CP_WAIT0();
    __syncthreads();
    issueA(0, 0);
    CP_COMMIT();

    const int rq = lane >> 2;
    const int cb = (lane & 2) * 2;
    const bool evn = !(lane & 1);
    int i = 0;
    while (true) {
        const int s = i & 1;
        const int ps = i % 3;
        const int k = __ldg(&g_ttap[u]);
        CP_WAIT0();
        __syncthreads();

        int un = u + SCGRID;
        bool hn = (un < ntiles);
        if (hn) {
            issueA(s ^ 1, (i + 1) % 3);
            int un2 = un + SCGRID;
            if (un2 < ntiles) issuePairs(un2, (i + 2) % 3);
            CP_COMMIT();
        }

        float acc[2][4][4];
        #pragma unroll
        for (int a = 0; a < 2; ++a)
            #pragma unroll
            for (int b = 0; b < 4; ++b)
                #pragma unroll
                for (int q = 0; q < 4; ++q) acc[a][b][q] = 0.f;

        const uint32_t ab = sb + SCA(s);
        const uint4* wfk = wf + ((size_t)(k * 2 + wg) * 16) * 32;
        #pragma unroll
        for (int kc = 0; kc < 4; ++kc) {
            uint32_t ah[2][4];
            #pragma unroll
            for (int mi = 0; mi < 2; ++mi)
                ldm_x4(ah[mi], ab + aoff[kc][mi]);
            const uint4* p = wfk + kc * 128;
            uint4 h0 = __ldg(p + lane);
            uint4 h1 = __ldg(p + 32 + lane);
            uint4 l0 = __ldg(p + 64 + lane);
            uint4 l1 = __ldg(p + 96 + lane);
            uint32_t bh[2][4] = {{h0.x, h0.y, h0.z, h0.w}, {h1.x, h1.y, h1.z, h1.w}};
            uint32_t bl[2][4] = {{l0.x, l0.y, l0.z, l0.w}, {l1.x, l1.y, l1.z, l1.w}};
            #pragma unroll
            for (int mi = 0; mi < 2; ++mi)
                #pragma unroll
                for (int nt = 0; nt < 4; ++nt) {
                    int ni = nt >> 1, ss = nt & 1;
                    mma_f16(acc[mi][nt], ah[mi], bh[ni][ss], bh[ni][ss + 2]);
                    mma_f16(acc[mi][nt], ah[mi], bl[ni][ss], bl[ni][ss + 2]);
                }
        }

        const int2* prs = (const int2*)(smem + SCP(ps));
        #pragma unroll
        for (int mi = 0; mi < 2; ++mi) {
            int r = m0 + mi * 16 + rq;
            int2 p0 = prs[r];
            int2 p1 = prs[r + 8];
            float* o0 = out + (size_t)p0.x * CCH;
            float* o1 = out + (size_t)p1.x * CCH;
            #pragma unroll
            for (int nt = 0; nt < 4; ++nt) {
                float a0 = acc[mi][nt][0], a1 = acc[mi][nt][1];
                float a2 = acc[mi][nt][2], a3 = acc[mi][nt][3];
                float b0 = __shfl_xor_sync(0xffffffffu, a0, 1);
                float b1 = __shfl_xor_sync(0xffffffffu, a1, 1);
                float b2 = __shfl_xor_sync(0xffffffffu, a2, 1);
                float b3 = __shfl_xor_sync(0xffffffffu, a3, 1);
                int col = nb0 + nt * 8 + cb;
                if (evn) {
                    if (p0.y >= 0) redadd4(o0 + col, a0, a1, b0, b1);
                } else {
                    if (p1.y >= 0) redadd4(o1 + col, b2, b3, a2, a3);
                }
            }
        }
        if (!hn) break;
        u = un;
        ++i;
    }
}

// ---------------- bnrelu: BN + ReLU fused, writes fp16 -------------------------
__global__ __launch_bounds__(256) void bnrelu_kernel(const float* __restrict__ x, int nchunk)
{
    int i = blockIdx.x * blockDim.x + threadIdx.x;
    if (i >= nchunk) return;
    const float4* x4 = (const float4*)x;
    float4 a = x4[2 * i], b = x4[2 * i + 1];
    int c = (i * 8) & 63;
    a.x = fmaxf(a.x * g_stats[c + 0] + g_stats[64 + c + 0], 0.f);
    a.y = fmaxf(a.y * g_stats[c + 1] + g_stats[64 + c + 1], 0.f);
    a.z = fmaxf(a.z * g_stats[c + 2] + g_stats[64 + c + 2], 0.f);
    a.w = fmaxf(a.w * g_stats[c + 3] + g_stats[64 + c + 3], 0.f);
    b.x = fmaxf(b.x * g_stats[c + 4] + g_stats[64 + c + 4], 0.f);
    b.y = fmaxf(b.y * g_stats[c + 5] + g_stats[64 + c + 5], 0.f);
    b.z = fmaxf(b.z * g_stats[c + 6] + g_stats[64 + c + 6], 0.f);
    b.w = fmaxf(b.w * g_stats[c + 7] + g_stats[64 + c + 7], 0.f);
    g_xh[i] = cvt8(a, b);
}

// ---------------- BN stats (deterministic) ------------------------------------
__global__ __launch_bounds__(256) void stats_kernel(const float* __restrict__ buf, int n)
{
    __shared__ float s[4][128];
    const int tid = threadIdx.x, lane = tid & 63, grp = tid >> 6;
    const int chunk = (n + SBLK - 1) / SBLK;
    const int r0 = blockIdx.x * chunk;
    const int r1 = min(r0 + chunk, n);
    float sm = 0.f, sq = 0.f;
    for (int r = r0 + grp; r < r1; r += 4) {
        float v = buf[(size_t)r * CCH + lane];
        sm += v; sq += v * v;
    }
    s[grp][lane] = sm; s[grp][64 + lane] = sq;
    __syncthreads();
    if (tid < 128)
        g_part[(size_t)blockIdx.x * 128 + tid] = s[0][tid] + s[1][tid] + s[2][tid] + s[3][tid];
}

__global__ __launch_bounds__(512) void reduce_kernel(
    const float* __restrict__ gamma, const float* __restrict__ beta, int n)
{
    __shared__ float s[4][128];
    const int tid = threadIdx.x, col = tid & 127, grp = tid >> 7;
    float acc = 0.f;
    for (int b = grp; b < SBLK; b += 4) acc += g_part[(size_t)b * 128 + col];
    s[grp][col] = acc;
    __syncthreads();
    if (tid < 128) s[0][tid] = s[0][tid] + s[1][tid] + s[2][tid] + s[3][tid];
    __syncthreads();
    if (tid < 64) {
        float inv_n = 1.0f / (float)n;
        float mean = s[0][tid] * inv_n;
        float var = s[0][64 + tid] * inv_n - mean * mean;
        float scale = gamma[tid] * rsqrtf(var + 1e-5f);
        g_stats[tid] = scale;
        g_stats[64 + tid] = beta[tid] - mean * scale;
    }
}

// ---------------- final: BN2 + residual + ReLU --------------------------------
__global__ __launch_bounds__(256) void final_kernel(
    const float* __restrict__ x, const float* __restrict__ feat,
    float* __restrict__ y, int total4)
{
    int i = blockIdx.x * blockDim.x + threadIdx.x;
    if (i >= total4) return;
    float4 v = reinterpret_cast<const float4*>(x)[i];
    float4 f = reinterpret_cast<const float4*>(feat)[i];
    int c = (i * 4) & 63;
    float4 o;
    o.x = fmaxf(v.x * g_stats[c + 0] + g_stats[64 + c + 0] + f.x, 0.f);
    o.y = fmaxf(v.y * g_stats[c + 1] + g_stats[64 + c + 1] + f.y, 0.f);
    o.z = fmaxf(v.z * g_stats[c + 2] + g_stats[64 + c + 2] + f.z, 0.f);
    o.w = fmaxf(v.w * g_stats[c + 3] + g_stats[64 + c + 3] + f.w, 0.f);
    reinterpret_cast<float4*>(y)[i] = o;
}

// ---------------- launch ------------------------------------------------------
extern "C" void kernel_launch(void* const* d_in, const int* in_sizes, int n_in,
                              void* d_out, int out_size)
{
    const float* feat   = (const float*)d_in[0];
    const int*   nbr    = (const int*)  d_in[1];
    const float* valid  = (const float*)d_in[2];
    const float* W1     = (const float*)d_in[3];
    const float* gamma1 = (const float*)d_in[4];
    const float* beta1  = (const float*)d_in[5];
    const float* W2     = (const float*)d_in[6];
    const float* gamma2 = (const float*)d_in[7];
    const float* beta2  = (const float*)d_in[8];
    float* out = (float*)d_out;

    const int n = in_sizes[0] / CCH;
    const int nchunk = n * 8;
    const int total4 = (n * CCH) / 4;
    const int xb = (nchunk + 255) / 256;
    const int cenBlocks = (n + 127) / 128;

    float *buf1; uint4 *xh, *wt1, *wt2, *wfb;
    cudaGetSymbolAddress((void**)&buf1, g_buf1);
    cudaGetSymbolAddress((void**)&xh, g_xh);
    cudaGetSymbolAddress((void**)&wt1, g_wt1);
    cudaGetSymbolAddress((void**)&wt2, g_wt2);
    cudaGetSymbolAddress((void**)&wfb, g_wf);

    cudaFuncSetAttribute(fillcen_kernel, cudaFuncAttributeMaxDynamicSharedMemorySize, CEN_SMEM);
    cudaFuncSetAttribute(center_kernel, cudaFuncAttributeMaxDynamicSharedMemorySize, CEN_SMEM);
    cudaFuncSetAttribute(scatter_kernel, cudaFuncAttributeMaxDynamicSharedMemorySize, SC_SMEM);

    dim3 ewGrid((total4 + 255) / 256);
    dim3 bnGrid((nchunk + 255) / 256);

    // profiled launch index is 3 -> scatter_kernel (conv1)
    prepcount_kernel<<<54 + xb + FBLK, 256>>>(W1, W2, feat, valid, nchunk, xb, n); // 0
    scan_kernel<<<1, 1024>>>();                                                    // 1
    fillcen_kernel<<<FBLK + cenBlocks + 108, 256, CEN_SMEM>>>(
        nbr, valid, xh, wt1 + 13 * 1024, buf1, n);                                 // 2
    scatter_kernel<<<SCGRID, 256, SC_SMEM>>>(xh, wfb, buf1);                       // 3 <- profiled
    stats_kernel<<<SBLK, 256>>>(buf1, n);                                          // 4
    reduce_kernel<<<1, 512>>>(gamma1, beta1, n);                                   // 5
    bnrelu_kernel<<<bnGrid, 256>>>(buf1, nchunk);                                  // 6

    // conv2
    center_kernel<<<cenBlocks, 256, CEN_SMEM>>>(xh, wt2 + 13 * 1024, buf1, n);     // 7
    scatter_kernel<<<SCGRID, 256, SC_SMEM>>>(xh, wfb + 27 * 2 * 16 * 32, buf1);    // 8
    stats_kernel<<<SBLK, 256>>>(buf1, n);                                          // 9
    reduce_kernel<<<1, 512>>>(gamma2, beta2, n);                                   // 10
    final_kernel<<<ewGrid, 256>>>(buf1, feat, out, total4);                        // 11
}

// round 16
// speedup vs baseline: 1.2678x; 1.0705x over previous
#include <cuda_runtime.h>
#include <cuda_fp16.h>
#include <cstdint>
#include <math.h>

#define NVOX   500000
#define CCH    64
#define KTAPS  27
#define SBLK   512
#define SCGRID 2048
#define FBLK   1664
#define MAXTIL 110000

// ---------------- static device scratch (no allocs allowed) -----------------
__device__ float g_buf1[(size_t)NVOX * CCH];      // conv out fp32 (pre-BN)
__device__ uint4 g_xh[(size_t)NVOX * 8];          // fp16 features [n][64]
__device__ uint4 g_wt1[KTAPS * 512];              // W1^T fp16, swizzled
__device__ uint4 g_wt2[KTAPS * 512];              // W2^T fp16, swizzled
__device__ uint4 g_wf[(size_t)2 * 27 * 2 * 256];  // W mma fragments
__device__ float g_part[SBLK * 128];
__device__ float g_stats[128];
__device__ int2  g_pairs[(size_t)NVOX * KTAPS];   // compacted (out,in), padded/128
__device__ int   g_bcnt[26 * 512];
__device__ int   g_boff[26 * 512];
__device__ int   g_meta[128];
__device__ int   g_tmap[MAXTIL];
__device__ int   g_ttap[MAXTIL];

// ---------------- helpers ----------------------------------------------------
__device__ __forceinline__ uint32_t smem_u32(const void* p) {
    uint32_t a;
    asm("{ .reg .u64 t; cvta.to.shared.u64 t, %1; cvt.u32.u64 %0, t; }" : "=r"(a) : "l"(p));
    return a;
}
__device__ __host__ __forceinline__ uint32_t sw128(uint32_t off) {
    return off ^ ((off >> 3) & 0x70);
}
__device__ __forceinline__ void ldm_x4(uint32_t* r, uint32_t addr) {
    asm volatile("ldmatrix.sync.aligned.m8n8.x4.shared.b16 {%0,%1,%2,%3}, [%4];"
                 : "=r"(r[0]), "=r"(r[1]), "=r"(r[2]), "=r"(r[3]) : "r"(addr));
}
__device__ __forceinline__ void mma_f16(float* d, const uint32_t* a,
                                        uint32_t b0, uint32_t b1) {
    asm volatile("mma.sync.aligned.m16n8k16.row.col.f32.f16.f16.f32 "
                 "{%0,%1,%2,%3}, {%4,%5,%6,%7}, {%8,%9}, {%0,%1,%2,%3};"
                 : "+f"(d[0]), "+f"(d[1]), "+f"(d[2]), "+f"(d[3])
                 : "r"(a[0]), "r"(a[1]), "r"(a[2]), "r"(a[3]), "r"(b0), "r"(b1));
}
__device__ __forceinline__ void cpa16(uint32_t dst, const void* src, uint32_t sz) {
    asm volatile("cp.async.cg.shared.global [%0], [%1], 16, %2;"
                 :: "r"(dst), "l"(src), "r"(sz) : "memory");
}
#define CP_COMMIT() asm volatile("cp.async.commit_group;" ::: "memory")
#define CP_WAIT0()  asm volatile("cp.async.wait_group 0;" ::: "memory")
__device__ __forceinline__ void redadd4(float* p, float x, float y, float z, float w) {
    asm volatile("red.global.v4.f32.add [%0], {%1,%2,%3,%4};"
                 :: "l"(p), "f"(x), "f"(y), "f"(z), "f"(w) : "memory");
}

// 8 floats -> 8 fp16 packed in one uint4
__device__ __forceinline__ uint4 cvt8(const float4& a, const float4& b)
{
    __half2 h0 = __floats2half2_rn(a.x, a.y);
    __half2 h1 = __floats2half2_rn(a.z, a.w);
    __half2 h2 = __floats2half2_rn(b.x, b.y);
    __half2 h3 = __floats2half2_rn(b.z, b.w);
    return make_uint4(*(uint32_t*)&h0, *(uint32_t*)&h1, *(uint32_t*)&h2, *(uint32_t*)&h3);
}

// 1-pass MMA over one 128x64x64 tile: A fp16 + W fp16 in smem
__device__ __forceinline__ void tile_mma1(
    uint32_t ab, uint32_t wh,
    const uint32_t aoff[4][2], const uint32_t boff[4][2], float acc[2][4][4])
{
    #pragma unroll
    for (int kc = 0; kc < 4; ++kc) {
        uint32_t ah[2][4], bh[2][4];
        #pragma unroll
        for (int mi = 0; mi < 2; ++mi)
            ldm_x4(ah[mi], ab + aoff[kc][mi]);
        #pragma unroll
        for (int ni = 0; ni < 2; ++ni)
            ldm_x4(bh[ni], wh + boff[kc][ni]);
        #pragma unroll
        for (int mi = 0; mi < 2; ++mi)
            #pragma unroll
            for (int nt = 0; nt < 4; ++nt) {
                int ni = nt >> 1, s = nt & 1;
                mma_f16(acc[mi][nt], ah[mi], bh[ni][s], bh[ni][s + 2]);
            }
    }
}

// ---------------- fused prep+count ---------------------------------------------
__global__ __launch_bounds__(256) void prepcount_kernel(
    const float* __restrict__ W1, const float* __restrict__ W2,
    const float* __restrict__ x, const float* __restrict__ valid,
    int nchunk, int xb, int n)
{
    const int b = blockIdx.x;
    if (b < 54) {
        const int k = (b < 27) ? b : b - 27;
        const float* W = (b < 27) ? W1 : W2;
        uint4* wt = (b < 27) ? g_wt1 : g_wt2;
        char* dst = (char*)(wt + (size_t)k * 512);
        for (int e = threadIdx.x; e < CCH * CCH; e += 256) {
            int ci = e >> 6, co = e & 63;
            float w = W[(size_t)k * CCH * CCH + e];
            __half h = __float2half_rn(w);
            uint32_t off = sw128((uint32_t)(co * 128 + ci * 2));
            *(__half*)(dst + off) = h;
        }
    } else if (b < 54 + xb) {
        int i = (b - 54) * 256 + threadIdx.x;
        if (i >= nchunk) return;
        const float4* x4 = (const float4*)x;
        g_xh[i] = cvt8(x4[2 * i], x4[2 * i + 1]);
    } else {
        const int cb = b - 54 - xb;
        const int kk = cb >> 6, bb = cb & 63;
        const int k = kk + (kk >= 13 ? 1 : 0);
        const int chunk = (n + 63) >> 6;
        const int r0 = bb * chunk, r1 = min(r0 + chunk, n);
        const int lane = threadIdx.x & 31, w = threadIdx.x >> 5;
        const int wc = (chunk + 7) >> 3;
        const int ws = r0 + w * wc, we = min(ws + wc, r1);
        const size_t kb = (size_t)k * n;
        int c = 0;
        for (int s = ws; s < we; s += 32) {
            int i = s + lane;
            bool v = (i < we) && (valid[kb + i] != 0.f);
            c += __popc(__ballot_sync(0xffffffffu, v));
        }
        if (lane == 0)
            g_bcnt[(size_t)cb * 8 + w] = c;
    }
}

// scan + layer-major map
__global__ __launch_bounds__(1024) void scan_kernel()
{
    __shared__ int stot[26];
    __shared__ int stb[27];
    const int tid = threadIdx.x, wid = tid >> 5, lane = tid & 31;
    int v[16], lexcl = 0;
    if (wid < 26) {
        const int base = wid * 512 + lane * 16;
        int s = 0;
        #pragma unroll
        for (int j = 0; j < 16; ++j) { v[j] = g_bcnt[base + j]; s += v[j]; }
        int p = s;
        #pragma unroll
        for (int d = 1; d < 32; d <<= 1) {
            int t = __shfl_up_sync(0xffffffffu, p, d);
            if (lane >= d) p += t;
        }
        lexcl = p - s;
        int tot = __shfl_sync(0xffffffffu, p, 31);
        if (lane == 0) stot[wid] = tot;
    }
    __syncthreads();
    if (tid == 0) {
        int tb = 0;
        for (int kk = 0; kk < 26; ++kk) {
            stb[kk] = tb;
            tb += (stot[kk] + 127) >> 7;
            g_meta[64 + kk] = stot[kk];
        }
        stb[26] = tb;
        for (int kk = 0; kk <= 26; ++kk) g_meta[kk] = stb[kk];
    }
    __syncthreads();
    if (wid < 26) {
        const int base = wid * 512 + lane * 16;
        int off = stb[wid] * 128 + lexcl;
        #pragma unroll
        for (int j = 0; j < 16; ++j) { g_boff[base + j] = off; off += v[j]; }
    }
    for (int kk = 0; kk < 26; ++kk) {
        const int tk = stb[kk + 1] - stb[kk];
        for (int j = tid; j < tk; j += 1024) {
            int pos = 0;
            #pragma unroll
            for (int q = 0; q < 26; ++q) {
                int tq = stb[q + 1] - stb[q];
                pos += min(tq, j);
                pos += (q < kk && tq > j) ? 1 : 0;
            }
            g_tmap[pos] = stb[kk] + j;
            g_ttap[pos] = kk + (kk >= 13 ? 1 : 0);
        }
    }
}

// ---------------- fused fill + center1 + wfrag ---------------------------------
#define CEN_SMEM 24576
__global__ __launch_bounds__(256, 2) void fillcen_kernel(
    const int* __restrict__ nbr, const float* __restrict__ valid,
    const uint4* __restrict__ xh, const uint4* __restrict__ wtap,
    float* __restrict__ out, int n)
{
    const int cenB = (n + 127) >> 7;
    if (blockIdx.x < FBLK) {
        const int cb = blockIdx.x;
        const int kk = cb >> 6, bb = cb & 63;
        const int k = kk + (kk >= 13 ? 1 : 0);
        const int chunk = (n + 63) >> 6;
        const int r0 = bb * chunk, r1 = min(r0 + chunk, n);
        const int lane = threadIdx.x & 31, w = threadIdx.x >> 5;
        const int wc = (chunk + 7) >> 3;
        const int ws = r0 + w * wc, we = min(ws + wc, r1);
        const size_t kb = (size_t)k * n;

        int off = g_boff[(size_t)cb * 8 + w];
        for (int s = ws; s < we; s += 32) {
            int i = s + lane;
            bool v = (i < we) && (valid[kb + i] != 0.f);
            unsigned bal = __ballot_sync(0xffffffffu, v);
            if (v)
                g_pairs[off + __popc(bal & ((1u << lane) - 1u))] = make_int2(i, nbr[kb + i]);
            off += __popc(bal);
        }
        if (bb == 63) {
            const int cnt = g_meta[64 + kk];
            const int sbase = g_meta[kk] * 128;
            const int padded = (g_meta[kk + 1] - g_meta[kk]) * 128;
            for (int s = cnt + threadIdx.x; s < padded; s += 256)
                g_pairs[sbase + s] = make_int2(0, -1);
        }
        return;
    }

    extern __shared__ char smem[];
    const uint32_t sb = smem_u32(smem);
    const int tid = threadIdx.x, lane = tid & 31, wid = tid >> 5;

    if (blockIdx.x >= FBLK + cenB) {
        // wfrag: store W mma fragments (fp16)
        const int task = blockIdx.x - FBLK - cenB;   // 0..107
        const int conv = task / 54;
        const int k = (task % 54) >> 1;
        const int g = task & 1;
        const uint4* wt = conv ? g_wt2 : g_wt1;
        uint4* s4 = (uint4*)smem;
        for (int e = tid; e < 512; e += 256)
            s4[e] = wt[(size_t)k * 512 + e];
        __syncthreads();
        if (wid == 0) {
            const uint32_t arow = lane & 15, agrp = (lane >> 4) * 16;
            const int nb0 = g * 32;
            uint4* dst = g_wf + (size_t)((conv * 27 + k) * 2 + g) * 256;
            #pragma unroll
            for (int kc = 0; kc < 4; ++kc) {
                uint32_t bh[2][4];
                #pragma unroll
                for (int ni = 0; ni < 2; ++ni) {
                    uint32_t off = sw128((uint32_t)((nb0 + ni * 16 + arow) * 128 + kc * 32) + agrp);
                    ldm_x4(bh[ni], sb + off);
                }
                uint4* d = dst + kc * 64;
                d[lane]      = make_uint4(bh[0][0], bh[0][1], bh[0][2], bh[0][3]);
                d[32 + lane] = make_uint4(bh[1][0], bh[1][1], bh[1][2], bh[1][3]);
            }
        }
        return;
    }

    // center1: dense identity-tap GEMM, fp16
    const int n0 = (blockIdx.x - FBLK) * 128;
    const int m0 = (wid & 3) * 32, nb0 = (wid >> 2) * 32;
    const int frow = tid >> 1, fhalf = tid & 1;

    const int g = n0 + frow;
    const uint32_t sz = (g < n) ? 16u : 0u;
    const int gc = min(g, n - 1);
    const char* sh = (const char*)(xh + (size_t)gc * 8);
    #pragma unroll
    for (int j = 0; j < 4; ++j) {
        int c = fhalf * 4 + j;
        cpa16(sb + sw128((uint32_t)(frow * 128 + c * 16)), sh + c * 16, sz);
    }
    const char* ws = (const char*)wtap;
    #pragma unroll
    for (int j = 0; j < 2; ++j) {
        int c = tid + j * 256;          // 0..511
        cpa16(sb + 16384 + c * 16, ws + c * 16, 16);
    }
    CP_COMMIT(); CP_WAIT0();
    __syncthreads();

    const uint32_t arow = lane & 15, agrp = (lane >> 4) * 16;
    uint32_t aoff[4][2], boff[4][2];
    #pragma unroll
    for (int kc = 0; kc < 4; ++kc) {
        #pragma unroll
        for (int mi = 0; mi < 2; ++mi)
            aoff[kc][mi] = sw128((uint32_t)((m0 + mi * 16 + arow) * 128 + kc * 32) + agrp);
        #pragma unroll
        for (int ni = 0; ni < 2; ++ni)
            boff[kc][ni] = sw128((uint32_t)((nb0 + ni * 16 + arow) * 128 + kc * 32) + agrp);
    }

    float acc[2][4][4];
    #pragma unroll
    for (int i = 0; i < 2; ++i)
        #pragma unroll
        for (int j = 0; j < 4; ++j)
            #pragma unroll
            for (int q = 0; q < 4; ++q) acc[i][j][q] = 0.f;

    tile_mma1(sb, sb + 16384, aoff, boff, acc);

    const int rq = lane >> 2, cq = (lane & 3) * 2;
    #pragma unroll
    for (int mi = 0; mi < 2; ++mi)
        #pragma unroll
        for (int nt = 0; nt < 4; ++nt) {
            int col = nb0 + nt * 8 + cq;
            int r0 = n0 + m0 + mi * 16 + rq;
            if (r0 < n)
                *(float2*)(out + (size_t)r0 * CCH + col) = make_float2(acc[mi][nt][0], acc[mi][nt][1]);
            int r1 = r0 + 8;
            if (r1 < n)
                *(float2*)(out + (size_t)r1 * CCH + col) = make_float2(acc[mi][nt][2], acc[mi][nt][3]);
        }
}

// ---------------- standalone center (conv2) ------------------------------------
__global__ __launch_bounds__(256, 2) void center_kernel(
    const uint4* __restrict__ xh, const uint4* __restrict__ wtap,
    float* __restrict__ out, int n)
{
    extern __shared__ char smem[];
    const uint32_t sb = smem_u32(smem);
    const int tid = threadIdx.x, lane = tid & 31, wid = tid >> 5;
    const int n0 = blockIdx.x * 128;
    const int m0 = (wid & 3) * 32, nb0 = (wid >> 2) * 32;
    const int frow = tid >> 1, fhalf = tid & 1;

    const int g = n0 + frow;
    const uint32_t sz = (g < n) ? 16u : 0u;
    const int gc = min(g, n - 1);
    const char* sh = (const char*)(xh + (size_t)gc * 8);
    #pragma unroll
    for (int j = 0; j < 4; ++j) {
        int c = fhalf * 4 + j;
        cpa16(sb + sw128((uint32_t)(frow * 128 + c * 16)), sh + c * 16, sz);
    }
    const char* ws = (const char*)wtap;
    #pragma unroll
    for (int j = 0; j < 2; ++j) {
        int c = tid + j * 256;
        cpa16(sb + 16384 + c * 16, ws + c * 16, 16);
    }
    CP_COMMIT(); CP_WAIT0();
    __syncthreads();

    const uint32_t arow = lane & 15, agrp = (lane >> 4) * 16;
    uint32_t aoff[4][2], boff[4][2];
    #pragma unroll
    for (int kc = 0; kc < 4; ++kc) {
        #pragma unroll
        for (int mi = 0; mi < 2; ++mi)
            aoff[kc][mi] = sw128((uint32_t)((m0 + mi * 16 + arow) * 128 + kc * 32) + agrp);
        #pragma unroll
        for (int ni = 0; ni < 2; ++ni)
            boff[kc][ni] = sw128((uint32_t)((nb0 + ni * 16 + arow) * 128 + kc * 32) + agrp);
    }

    float acc[2][4][4];
    #pragma unroll
    for (int i = 0; i < 2; ++i)
        #pragma unroll
        for (int j = 0; j < 4; ++j)
            #pragma unroll
            for (int q = 0; q < 4; ++q) acc[i][j][q] = 0.f;

    tile_mma1(sb, sb + 16384, aoff, boff, acc);

    const int rq = lane >> 2, cq = (lane & 3) * 2;
    #pragma unroll
    for (int mi = 0; mi < 2; ++mi)
        #pragma unroll
        for (int nt = 0; nt < 4; ++nt) {
            int col = nb0 + nt * 8 + cq;
            int r0 = n0 + m0 + mi * 16 + rq;
            if (r0 < n)
                *(float2*)(out + (size_t)r0 * CCH + col) = make_float2(acc[mi][nt][0], acc[mi][nt][1]);
            int r1 = r0 + 8;
            if (r1 < n)
                *(float2*)(out + (size_t)r1 * CCH + col) = make_float2(acc[mi][nt][2], acc[mi][nt][3]);
        }
}

// ---------------- scatter conv: fp16 1-pass W, layer-major --------------------
#define SCA(s)     ((s) * 16384)            // A stage fp16: 16KB
#define SCP(ps)    (32768 + (ps) * 1024)    // pairs, 3 stages
#define SC_SMEM    35840

__global__ __launch_bounds__(256, 3) void scatter_kernel(
    const uint4* __restrict__ xh, const uint4* __restrict__ wf,
    float* __restrict__ out)
{
    extern __shared__ char smem[];
    const uint32_t sb = smem_u32(smem);
    const int tid = threadIdx.x, lane = tid & 31, wid = tid >> 5;
    const int m0 = (wid & 3) * 32, nb0 = (wid >> 2) * 32;
    const int wg = wid >> 2;
    const int frow = tid >> 1, fhalf = tid & 1;

    const int ntiles = g_meta[26];
    int u = blockIdx.x;
    if (u >= ntiles) return;

    const uint32_t arow = lane & 15, agrp = (lane >> 4) * 16;
    uint32_t aoff[4][2];
    #pragma unroll
    for (int kc = 0; kc < 4; ++kc)
        #pragma unroll
        for (int mi = 0; mi < 2; ++mi)
            aoff[kc][mi] = sw128((uint32_t)((m0 + mi * 16 + arow) * 128 + kc * 32) + agrp);
    uint32_t so4[4];
    #pragma unroll
    for (int j = 0; j < 4; ++j)
        so4[j] = sw128((uint32_t)(frow * 128 + (fhalf * 4 + j) * 16));

    auto issuePairs = [&](int uu, int ps) {
        int tt = __ldg(&g_tmap[uu]);
        if (tid < 64)
            cpa16(sb + SCP(ps) + tid * 16,
                  (const char*)(g_pairs + (size_t)tt * 128) + tid * 16, 16);
    };
    auto issueA = [&](int s, int ps) {
        const int2* prs = (const int2*)(smem + SCP(ps));
        int in = prs[frow].y;
        uint32_t sz = (in >= 0) ? 16u : 0u;
        int ic = (in >= 0) ? in : 0;
        const char* sh = (const char*)(xh + (size_t)ic * 8);
        #pragma unroll
        for (int j = 0; j < 4; ++j)
            cpa16(sb + SCA(s) + so4[j], sh + (fhalf * 4 + j) * 16, sz);
    };

    // prologue
    issuePairs(u, 0);
    if (u + SCGRID < ntiles) issuePairs(u + SCGRID, 1);
    CP_COMMIT(); CP_WAIT0();
    __syncthreads();
    issueA(0, 0);
    CP_COMMIT();

    const int rq = lane >> 2;
    const int cb = (lane & 2) * 2;
    const bool evn = !(lane & 1);
    int i = 0;
    while (true) {
        const int s = i & 1;
        const int ps = i % 3;
        const int k = __ldg(&g_ttap[u]);
        CP_WAIT0();
        __syncthreads();

        int un = u + SCGRID;
        bool hn = (un < ntiles);
        if (hn) {
            issueA(s ^ 1, (i + 1) % 3);
            int un2 = un + SCGRID;
            if (un2 < ntiles) issuePairs(un2, (i + 2) % 3);
            CP_COMMIT();
        }

        float acc[2][4][4];
        #pragma unroll
        for (int a = 0; a < 2; ++a)
            #pragma unroll
            for (int b = 0; b < 4; ++b)
                #pragma unroll
                for (int q = 0; q < 4; ++q) acc[a][b][q] = 0.f;

        const uint32_t ab = sb + SCA(s);
        const uint4* wfk = wf + (size_t)(k * 2 + wg) * 256;
        #pragma unroll
        for (int kc = 0; kc < 4; ++kc) {
            uint32_t ah[2][4];
            #pragma unroll
            for (int mi = 0; mi < 2; ++mi)
                ldm_x4(ah[mi], ab + aoff[kc][mi]);
            const uint4* p = wfk + kc * 64;
            uint4 h0 = __ldg(p + lane);
            uint4 h1 = __ldg(p + 32 + lane);
            uint32_t bh[2][4] = {{h0.x, h0.y, h0.z, h0.w}, {h1.x, h1.y, h1.z, h1.w}};
            #pragma unroll
            for (int mi = 0; mi < 2; ++mi)
                #pragma unroll
                for (int nt = 0; nt < 4; ++nt) {
                    int ni = nt >> 1, ss = nt & 1;
                    mma_f16(acc[mi][nt], ah[mi], bh[ni][ss], bh[ni][ss + 2]);
                }
        }

        const int2* prs = (const int2*)(smem + SCP(ps));
        #pragma unroll
        for (int mi = 0; mi < 2; ++mi) {
            int r = m0 + mi * 16 + rq;
            int2 p0 = prs[r];
            int2 p1 = prs[r + 8];
            float* o0 = out + (size_t)p0.x * CCH;
            float* o1 = out + (size_t)p1.x * CCH;
            #pragma unroll
            for (int nt = 0; nt < 4; ++nt) {
                float a0 = acc[mi][nt][0], a1 = acc[mi][nt][1];
                float a2 = acc[mi][nt][2], a3 = acc[mi][nt][3];
                float b0 = __shfl_xor_sync(0xffffffffu, a0, 1);
                float b1 = __shfl_xor_sync(0xffffffffu, a1, 1);
                float b2 = __shfl_xor_sync(0xffffffffu, a2, 1);
                float b3 = __shfl_xor_sync(0xffffffffu, a3, 1);
                int col = nb0 + nt * 8 + cb;
                if (evn) {
                    if (p0.y >= 0) redadd4(o0 + col, a0, a1, b0, b1);
                } else {
                    if (p1.y >= 0) redadd4(o1 + col, b2, b3, a2, a3);
                }
            }
        }
        if (!hn) break;
        u = un;
        ++i;
    }
}

// ---------------- bnrelu: BN + ReLU fused, writes fp16 -------------------------
__global__ __launch_bounds__(256) void bnrelu_kernel(const float* __restrict__ x, int nchunk)
{
    int i = blockIdx.x * blockDim.x + threadIdx.x;
    if (i >= nchunk) return;
    const float4* x4 = (const float4*)x;
    float4 a = x4[2 * i], b = x4[2 * i + 1];
    int c = (i * 8) & 63;
    a.x = fmaxf(a.x * g_stats[c + 0] + g_stats[64 + c + 0], 0.f);
    a.y = fmaxf(a.y * g_stats[c + 1] + g_stats[64 + c + 1], 0.f);
    a.z = fmaxf(a.z * g_stats[c + 2] + g_stats[64 + c + 2], 0.f);
    a.w = fmaxf(a.w * g_stats[c + 3] + g_stats[64 + c + 3], 0.f);
    b.x = fmaxf(b.x * g_stats[c + 4] + g_stats[64 + c + 4], 0.f);
    b.y = fmaxf(b.y * g_stats[c + 5] + g_stats[64 + c + 5], 0.f);
    b.z = fmaxf(b.z * g_stats[c + 6] + g_stats[64 + c + 6], 0.f);
    b.w = fmaxf(b.w * g_stats[c + 7] + g_stats[64 + c + 7], 0.f);
    g_xh[i] = cvt8(a, b);
}

// ---------------- BN stats (deterministic) ------------------------------------
__global__ __launch_bounds__(256) void stats_kernel(const float* __restrict__ buf, int n)
{
    __shared__ float s[4][128];
    const int tid = threadIdx.x, lane = tid & 63, grp = tid >> 6;
    const int chunk = (n + SBLK - 1) / SBLK;
    const int r0 = blockIdx.x * chunk;
    const int r1 = min(r0 + chunk, n);
    float sm = 0.f, sq = 0.f;
    for (int r = r0 + grp; r < r1; r += 4) {
        float v = buf[(size_t)r * CCH + lane];
        sm += v; sq += v * v;
    }
    s[grp][lane] = sm; s[grp][64 + lane] = sq;
    __syncthreads();
    if (tid < 128)
        g_part[(size_t)blockIdx.x * 128 + tid] = s[0][tid] + s[1][tid] + s[2][tid] + s[3][tid];
}

__global__ __launch_bounds__(512) void reduce_kernel(
    const float* __restrict__ gamma, const float* __restrict__ beta, int n)
{
    __shared__ float s[4][128];
    const int tid = threadIdx.x, col = tid & 127, grp = tid >> 7;
    float acc = 0.f;
    for (int b = grp; b < SBLK; b += 4) acc += g_part[(size_t)b * 128 + col];
    s[grp][col] = acc;
    __syncthreads();
    if (tid < 128) s[0][tid] = s[0][tid] + s[1][tid] + s[2][tid] + s[3][tid];
    __syncthreads();
    if (tid < 64) {
        float inv_n = 1.0f / (float)n;
        float mean = s[0][tid] * inv_n;
        float var = s[0][64 + tid] * inv_n - mean * mean;
        float scale = gamma[tid] * rsqrtf(var + 1e-5f);
        g_stats[tid] = scale;
        g_stats[64 + tid] = beta[tid] - mean * scale;
    }
}

// ---------------- final: BN2 + residual + ReLU --------------------------------
__global__ __launch_bounds__(256) void final_kernel(
    const float* __restrict__ x, const float* __restrict__ feat,
    float* __restrict__ y, int total4)
{
    int i = blockIdx.x * blockDim.x + threadIdx.x;
    if (i >= total4) return;
    float4 v = reinterpret_cast<const float4*>(x)[i];
    float4 f = reinterpret_cast<const float4*>(feat)[i];
    int c = (i * 4) & 63;
    float4 o;
    o.x = fmaxf(v.x * g_stats[c + 0] + g_stats[64 + c + 0] + f.x, 0.f);
    o.y = fmaxf(v.y * g_stats[c + 1] + g_stats[64 + c + 1] + f.y, 0.f);
    o.z = fmaxf(v.z * g_stats[c + 2] + g_stats[64 + c + 2] + f.z, 0.f);
    o.w = fmaxf(v.w * g_stats[c + 3] + g_stats[64 + c + 3] + f.w, 0.f);
    reinterpret_cast<float4*>(y)[i] = o;
}

// ---------------- launch ------------------------------------------------------
extern "C" void kernel_launch(void* const* d_in, const int* in_sizes, int n_in,
                              void* d_out, int out_size)
{
    const float* feat   = (const float*)d_in[0];
    const int*   nbr    = (const int*)  d_in[1];
    const float* valid  = (const float*)d_in[2];
    const float* W1     = (const float*)d_in[3];
    const float* gamma1 = (const float*)d_in[4];
    const float* beta1  = (const float*)d_in[5];
    const float* W2     = (const float*)d_in[6];
    const float* gamma2 = (const float*)d_in[7];
    const float* beta2  = (const float*)d_in[8];
    float* out = (float*)d_out;

    const int n = in_sizes[0] / CCH;
    const int nchunk = n * 8;
    const int total4 = (n * CCH) / 4;
    const int xb = (nchunk + 255) / 256;
    const int cenBlocks = (n + 127) / 128;

    float *buf1; uint4 *xh, *wt1, *wt2, *wfb;
    cudaGetSymbolAddress((void**)&buf1, g_buf1);
    cudaGetSymbolAddress((void**)&xh, g_xh);
    cudaGetSymbolAddress((void**)&wt1, g_wt1);
    cudaGetSymbolAddress((void**)&wt2, g_wt2);
    cudaGetSymbolAddress((void**)&wfb, g_wf);

    cudaFuncSetAttribute(fillcen_kernel, cudaFuncAttributeMaxDynamicSharedMemorySize, CEN_SMEM);
    cudaFuncSetAttribute(center_kernel, cudaFuncAttributeMaxDynamicSharedMemorySize, CEN_SMEM);
    cudaFuncSetAttribute(scatter_kernel, cudaFuncAttributeMaxDynamicSharedMemorySize, SC_SMEM);

    dim3 ewGrid((total4 + 255) / 256);
    dim3 bnGrid((nchunk + 255) / 256);

    // profiled launch index is 3 -> scatter_kernel (conv1)
    prepcount_kernel<<<54 + xb + FBLK, 256>>>(W1, W2, feat, valid, nchunk, xb, n); // 0
    scan_kernel<<<1, 1024>>>();                                                    // 1
    fillcen_kernel<<<FBLK + cenBlocks + 108, 256, CEN_SMEM>>>(
        nbr, valid, xh, wt1 + 13 * 512, buf1, n);                                  // 2
    scatter_kernel<<<SCGRID, 256, SC_SMEM>>>(xh, wfb, buf1);                       // 3 <- profiled
    stats_kernel<<<SBLK, 256>>>(buf1, n);                                          // 4
    reduce_kernel<<<1, 512>>>(gamma1, beta1, n);                                   // 5
    bnrelu_kernel<<<bnGrid, 256>>>(buf1, nchunk);                                  // 6

    // conv2
    center_kernel<<<cenBlocks, 256, CEN_SMEM>>>(xh, wt2 + 13 * 512, buf1, n);      // 7
    scatter_kernel<<<SCGRID, 256, SC_SMEM>>>(xh, wfb + 27 * 2 * 256, buf1);        // 8
    stats_kernel<<<SBLK, 256>>>(buf1, n);                                          // 9
    reduce_kernel<<<1, 512>>>(gamma2, beta2, n);                                   // 10
    final_kernel<<<ewGrid, 256>>>(buf1, feat, out, total4);                        // 11
}